// round 5
// baseline (speedup 1.0000x reference)
#include <cuda_runtime.h>
#include <cuda_bf16.h>
#include <cstdint>

// Problem constants
#define BATCH   512
#define CIN     128
#define LIN     1024
#define KW      5
#define LOUT    1020
#define TSEQ    1020
#define H1      32
#define H2      16
#define H3      32
#define MROWS   (BATCH * TSEQ)   // 522240

// ---------------- scratch ----------------
__device__ float g_conv[(size_t)BATCH * CIN * LOUT];
__device__ float g_xg1 [(size_t)MROWS * 4 * H1];
__device__ float g_wt  [5 * 128 * 128];   // prepacked conv W: [tap][co][ci], tf32 bits

// ---------------- helpers ----------------
__device__ __forceinline__ float sigmoid_fast(float x) {
    // 1/(1+e^-x); inf-safe (exp->inf => 0, exp->0 => 1)
    float e = __expf(-x);
    float r; asm("rcp.approx.f32 %0, %1;" : "=f"(r) : "f"(1.f + e));
    return r;
}
__device__ __forceinline__ float tanh_fast(float x) {
    // 1 - 2/(e^{2x}+1); inf-safe both directions
    float e = __expf(2.f * x);
    float r; asm("rcp.approx.f32 %0, %1;" : "=f"(r) : "f"(1.f + e));
    return fmaf(-2.f, r, 1.f);
}
__device__ __forceinline__ uint32_t f2tf32(float f) {
    uint32_t r;
    asm("cvt.rna.tf32.f32 %0, %1;" : "=r"(r) : "f"(f));
    return r;
}
__device__ __forceinline__ void mma_tf32(float c[4], const uint32_t a[4], uint32_t b0, uint32_t b1) {
    asm volatile(
        "mma.sync.aligned.m16n8k8.row.col.f32.tf32.tf32.f32 "
        "{%0,%1,%2,%3}, {%4,%5,%6,%7}, {%8,%9}, {%0,%1,%2,%3};"
        : "+f"(c[0]), "+f"(c[1]), "+f"(c[2]), "+f"(c[3])
        : "r"(a[0]), "r"(a[1]), "r"(a[2]), "r"(a[3]), "r"(b0), "r"(b1));
}
__device__ __forceinline__ float2 ffma2(float2 a, float2 b, float2 c) {
    unsigned long long ua, ub, uc, ur;
    ua = *reinterpret_cast<unsigned long long*>(&a);
    ub = *reinterpret_cast<unsigned long long*>(&b);
    uc = *reinterpret_cast<unsigned long long*>(&c);
    asm("fma.rn.f32x2 %0, %1, %2, %3;" : "=l"(ur) : "l"(ua), "l"(ub), "l"(uc));
    return *reinterpret_cast<float2*>(&ur);
}
__device__ __forceinline__ uint32_t smem_u32(const void* p) {
    uint32_t a;
    asm("{ .reg .u64 t; cvta.to.shared.u64 t, %1; cvt.u32.u64 %0, t; }" : "=r"(a) : "l"(p));
    return a;
}
__device__ __forceinline__ void cp16(uint32_t dst, const void* src) {
    asm volatile("cp.async.ca.shared.global [%0], [%1], 16;" :: "r"(dst), "l"(src));
}
__device__ __forceinline__ void cp16n(uint32_t dst, const void* src, int nbytes) {
    asm volatile("cp.async.ca.shared.global [%0], [%1], 16, %2;" :: "r"(dst), "l"(src), "r"(nbytes));
}

// =====================================================================
// W prepack for conv
// =====================================================================
__global__ void prep_w_kernel(const float* __restrict__ w) {
    int i = blockIdx.x * 256 + threadIdx.x;
    if (i < 5 * 128 * 128) {
        int ci = i & 127;
        int r  = i >> 7;
        int co  = r & 127;
        int tap = r >> 7;
        g_wt[i] = __uint_as_float(f2tf32(w[((size_t)co * 128 + ci) * 5 + tap]));
    }
}

// =====================================================================
// conv1d via tf32 MMA, 128co x 256l, cp.async double-buffered (as R4)
// =====================================================================
#define CV2_WS_ST   12800
#define CV2_XS_ST   (16 * 264)
#define CV2_XS_BASE (2 * CV2_WS_ST)
#define CV2_SMEM_BYTES ((2 * CV2_WS_ST + 2 * CV2_XS_ST) * 4)

__global__ __launch_bounds__(256, 1) void conv2_kernel(
    const float* __restrict__ x, const float* __restrict__ bias)
{
    extern __shared__ float smf[];
    const uint32_t sbase = smem_u32(smf);
    const uint32_t* Su = reinterpret_cast<const uint32_t*>(smf);

    const int b   = blockIdx.y;
    const int lb  = blockIdx.x * 256;
    const int tid = threadIdx.x;
    const int warp = tid >> 5;
    const int lane = tid & 31;
    const int g   = lane >> 2;
    const int t4  = lane & 3;
    const int warp_m = warp >> 1;
    const int warp_n = warp & 1;

    const float* xb = x + (size_t)b * (CIN * LIN);

    float acc[2][16][4];
#pragma unroll
    for (int mi = 0; mi < 2; mi++)
#pragma unroll
        for (int ni = 0; ni < 16; ni++)
#pragma unroll
            for (int e = 0; e < 4; e++) acc[mi][ni][e] = 0.f;

    auto issue_chunk = [&](int c, int s) {
#pragma unroll
        for (int i = 0; i < 10; i++) {
            int v = tid + i * 256;
            int row = v >> 2, q = v & 3;
            uint32_t d = sbase + (uint32_t)(s * CV2_WS_ST + row * 20 + q * 4) * 4;
            cp16(d, g_wt + (size_t)row * 128 + c * 16 + q * 4);
        }
#pragma unroll
        for (int i = 0; i < 5; i++) {
            int v = tid + i * 256;
            if (v < 1040) {
                int row = v / 65, q = v - row * 65;
                int gl = lb + q * 4;
                int nb = (LIN - gl) * 4;
                nb = nb < 0 ? 0 : (nb > 16 ? 16 : nb);
                const float* sp = (nb > 0) ? (xb + (size_t)(c * 16 + row) * LIN + gl) : xb;
                uint32_t d = sbase + (uint32_t)(CV2_XS_BASE + s * CV2_XS_ST + row * 264 + q * 4) * 4;
                cp16n(d, sp, nb);
            }
        }
    };

    for (int c = 0; c < 8; c++) {
        const int s = c & 1;
        if (c == 0) {
            issue_chunk(0, 0);
            asm volatile("cp.async.commit_group;");
        }
        if (c + 1 < 8) {
            issue_chunk(c + 1, s ^ 1);
            asm volatile("cp.async.commit_group;");
            asm volatile("cp.async.wait_group 1;");
        } else {
            asm volatile("cp.async.wait_group 0;");
        }
        __syncthreads();

        const uint32_t* Wst = Su + s * CV2_WS_ST;
        const uint32_t* Xst = Su + CV2_XS_BASE + s * CV2_XS_ST;
#pragma unroll
        for (int tap = 0; tap < 5; tap++) {
#pragma unroll
            for (int ks = 0; ks < 2; ks++) {
                const int k0 = ks * 8;
                uint32_t a[2][4];
#pragma unroll
                for (int mi = 0; mi < 2; mi++) {
                    int row = tap * 128 + warp_m * 32 + mi * 16;
                    a[mi][0] = Wst[(row + g)     * 20 + k0 + t4];
                    a[mi][1] = Wst[(row + 8 + g) * 20 + k0 + t4];
                    a[mi][2] = Wst[(row + g)     * 20 + k0 + t4 + 4];
                    a[mi][3] = Wst[(row + 8 + g) * 20 + k0 + t4 + 4];
                }
#pragma unroll
                for (int ni = 0; ni < 16; ni++) {
                    int col = warp_n * 128 + ni * 8 + g + tap;
                    uint32_t b0 = Xst[(k0 + t4)     * 264 + col];
                    uint32_t b1 = Xst[(k0 + t4 + 4) * 264 + col];
                    mma_tf32(acc[0][ni], a[0], b0, b1);
                    mma_tf32(acc[1][ni], a[1], b0, b1);
                }
            }
        }
        __syncthreads();
    }

    float* ob = g_conv + (size_t)b * (CIN * LOUT);
#pragma unroll
    for (int mi = 0; mi < 2; mi++) {
        int row0 = warp_m * 32 + mi * 16 + g;
        float bv0 = bias[row0];
        float bv1 = bias[row0 + 8];
#pragma unroll
        for (int ni = 0; ni < 16; ni++) {
            int l = lb + warp_n * 128 + ni * 8 + 2 * t4;
            if (l + 1 < LOUT) {
                *reinterpret_cast<float2*>(ob + (size_t)row0 * LOUT + l) =
                    make_float2(acc[mi][ni][0] + bv0, acc[mi][ni][1] + bv0);
                *reinterpret_cast<float2*>(ob + (size_t)(row0 + 8) * LOUT + l) =
                    make_float2(acc[mi][ni][2] + bv1, acc[mi][ni][3] + bv1);
            } else if (l < LOUT) {
                ob[(size_t)row0 * LOUT + l]       = acc[mi][ni][0] + bv0;
                ob[(size_t)(row0 + 8) * LOUT + l] = acc[mi][ni][2] + bv1;
            }
        }
    }
}

// =====================================================================
// xg1 GEMM via tf32 MMA (unchanged)
// =====================================================================
#define XG_STRIDE 132
#define XG_SMEM_BYTES (2 * 128 * XG_STRIDE * 4)

__global__ __launch_bounds__(256) void xg1_mma_kernel(
    const float* __restrict__ A, const float* __restrict__ W,
    const float* __restrict__ b1, const float* __restrict__ b2,
    float* __restrict__ C)
{
    extern __shared__ uint32_t smem_u[];
    uint32_t* As = smem_u;
    uint32_t* Bs = smem_u + 128 * XG_STRIDE;

    const int row0 = blockIdx.x * 128;
    const int tid  = threadIdx.x;
    const int warp = tid >> 5;
    const int lane = tid & 31;
    const int g    = lane >> 2;
    const int t4   = lane & 3;
    const int warp_m = warp >> 1;
    const int warp_n = warp & 1;

    for (int v = tid; v < 128 * 32; v += 256) {
        int r  = v >> 5;
        int k4 = (v & 31) * 4;
        float4 av = *reinterpret_cast<const float4*>(A + (size_t)(row0 + r) * 128 + k4);
        *reinterpret_cast<uint4*>(&As[r * XG_STRIDE + k4]) =
            make_uint4(f2tf32(av.x), f2tf32(av.y), f2tf32(av.z), f2tf32(av.w));
        float4 wv = *reinterpret_cast<const float4*>(W + (size_t)r * 128 + k4);
        *reinterpret_cast<uint4*>(&Bs[r * XG_STRIDE + k4]) =
            make_uint4(f2tf32(wv.x), f2tf32(wv.y), f2tf32(wv.z), f2tf32(wv.w));
    }
    __syncthreads();

    float acc[2][8][4];
#pragma unroll
    for (int mi = 0; mi < 2; mi++)
#pragma unroll
        for (int ni = 0; ni < 8; ni++)
#pragma unroll
            for (int e = 0; e < 4; e++) acc[mi][ni][e] = 0.f;

#pragma unroll
    for (int k0 = 0; k0 < 128; k0 += 8) {
        uint32_t a[2][4];
#pragma unroll
        for (int mi = 0; mi < 2; mi++) {
            int row = warp_m * 32 + mi * 16;
            a[mi][0] = As[(row + g)     * XG_STRIDE + k0 + t4];
            a[mi][1] = As[(row + 8 + g) * XG_STRIDE + k0 + t4];
            a[mi][2] = As[(row + g)     * XG_STRIDE + k0 + t4 + 4];
            a[mi][3] = As[(row + 8 + g) * XG_STRIDE + k0 + t4 + 4];
        }
#pragma unroll
        for (int ni = 0; ni < 8; ni++) {
            int n = warp_n * 64 + ni * 8 + g;
            uint32_t b0 = Bs[n * XG_STRIDE + k0 + t4];
            uint32_t b1 = Bs[n * XG_STRIDE + k0 + t4 + 4];
            mma_tf32(acc[0][ni], a[0], b0, b1);
            mma_tf32(acc[1][ni], a[1], b0, b1);
        }
    }

#pragma unroll
    for (int mi = 0; mi < 2; mi++) {
        int r0 = row0 + warp_m * 32 + mi * 16 + g;
#pragma unroll
        for (int ni = 0; ni < 8; ni++) {
            int n = warp_n * 64 + ni * 8 + 2 * t4;
            float bb0 = b1[n] + b2[n];
            float bb1 = b1[n + 1] + b2[n + 1];
            *reinterpret_cast<float2*>(C + (size_t)r0 * 128 + n) =
                make_float2(acc[mi][ni][0] + bb0, acc[mi][ni][1] + bb1);
            *reinterpret_cast<float2*>(C + (size_t)(r0 + 8) * 128 + n) =
                make_float2(acc[mi][ni][2] + bb0, acc[mi][ni][3] + bb1);
        }
    }
}

// =====================================================================
// Fused LSTM1+2+3, role-pipelined, ALL WEIGHTS IN SHARED MEMORY
// (no per-role register arrays -> no spills).
// Weight layouts (float2, gate-paired, k-major => conflict-free LDS):
//   w1if[k][j] = {Whh1[j][k],    Whh1[32+j][k]}   k<32, j<32
//   w1go[k][j] = {Whh1[64+j][k], Whh1[96+j][k]}
//   w3hif/w3hgo: same for Whh3
//   w2ip[k][j] = {Wih2[j][k], Wih2[32+j][k]}      k<32, j<32
//   w2hp[k][j] = {Whh2[j][k], Whh2[32+j][k]}      k<16, j<32
//   w3ia[k][j] = {Wih3[j][k],    Wih3[32+j][k]}   k<16, j<32
//   w3ib[k][j] = {Wih3[64+j][k], Wih3[96+j][k]}
// Hidden rings store duplicated {h,h} float2 for direct ffma2 operands.
// =====================================================================
#define FL_SMEM_BYTES 56320

__global__ __launch_bounds__(128) void fused_lstm_kernel(
    const float* __restrict__ xg1,
    const float* __restrict__ Whh1,
    const float* __restrict__ Wih2, const float* __restrict__ Whh2,
    const float* __restrict__ bih2, const float* __restrict__ bhh2,
    const float* __restrict__ Wih3, const float* __restrict__ Whh3,
    const float* __restrict__ bih3, const float* __restrict__ bhh3,
    float* __restrict__ out)
{
    extern __shared__ __align__(16) float2 sm2[];
    float2* w1if  = sm2;           // 1024
    float2* w1go  = sm2 + 1024;    // 1024
    float2* w3hif = sm2 + 2048;    // 1024
    float2* w3hgo = sm2 + 3072;    // 1024
    float2* w2ip  = sm2 + 4096;    // 1024
    float2* w2hp  = sm2 + 5120;    // 512
    float2* w3ia  = sm2 + 5632;    // 512
    float2* w3ib  = sm2 + 6144;    // 512
    float2* b2p   = sm2 + 6656;    // 32
    float2* b3a   = sm2 + 6688;    // 32
    float2* b3b   = sm2 + 6720;    // 32
    float2* h1d   = sm2 + 6752;    // [2][32]
    float2* h2d   = sm2 + 6816;    // [2][16]
    float2* h3d   = sm2 + 6848;    // [2][32]
    float*  pre3s = reinterpret_cast<float*>(sm2 + 6912);  // [2][128]

    const int tid  = threadIdx.x;
    const int wid  = tid >> 5;
    const int lane = tid & 31;
    const int b    = blockIdx.x;
    const int role = (wid + b) & 3;   // rotate roles across CTAs for SMSP balance

    // ---- cooperative weight load (one-time) ----
    for (int v = tid; v < 1024; v += 128) {
        int k = v >> 5, j = v & 31;
        w1if[v]  = make_float2(Whh1[(size_t)j * 32 + k],        Whh1[(size_t)(32 + j) * 32 + k]);
        w1go[v]  = make_float2(Whh1[(size_t)(64 + j) * 32 + k], Whh1[(size_t)(96 + j) * 32 + k]);
        w3hif[v] = make_float2(Whh3[(size_t)j * 32 + k],        Whh3[(size_t)(32 + j) * 32 + k]);
        w3hgo[v] = make_float2(Whh3[(size_t)(64 + j) * 32 + k], Whh3[(size_t)(96 + j) * 32 + k]);
        w2ip[v]  = make_float2(Wih2[(size_t)j * 32 + k],        Wih2[(size_t)(32 + j) * 32 + k]);
    }
    for (int v = tid; v < 512; v += 128) {
        int k = v >> 5, j = v & 31;
        w2hp[v] = make_float2(Whh2[(size_t)j * 16 + k],        Whh2[(size_t)(32 + j) * 16 + k]);
        w3ia[v] = make_float2(Wih3[(size_t)j * 16 + k],        Wih3[(size_t)(32 + j) * 16 + k]);
        w3ib[v] = make_float2(Wih3[(size_t)(64 + j) * 16 + k], Wih3[(size_t)(96 + j) * 16 + k]);
    }
    if (tid < 32) {
        b2p[tid] = make_float2(bih2[tid] + bhh2[tid],           bih2[32 + tid] + bhh2[32 + tid]);
        b3a[tid] = make_float2(bih3[tid] + bhh3[tid],           bih3[32 + tid] + bhh3[32 + tid]);
        b3b[tid] = make_float2(bih3[64 + tid] + bhh3[64 + tid], bih3[96 + tid] + bhh3[96 + tid]);
    }
    // zero rings
    for (int v = tid; v < 160; v += 128) h1d[v] = make_float2(0.f, 0.f);   // covers h1d,h2d,h3d (contiguous)
    for (int v = tid; v < 256; v += 128) pre3s[v] = 0.f;

    float cst = 0.f, h3loc = 0.f;
    float p0 = 0.f, p1 = 0.f, p2 = 0.f, p3 = 0.f;
    const float* xb = xg1 + (size_t)b * TSEQ * 128 + lane;
    if (role == 0) { p0 = xb[0]; p1 = xb[32]; p2 = xb[64]; p3 = xb[96]; }
    __syncthreads();

    for (int s = 0; s < TSEQ + 3; s++) {
        const int rs = (s - 1) & 1;
        const int ws = s & 1;

        if (role == 0) {
            if (s < TSEQ) {
                float2 aif = make_float2(p0, p1);
                float2 ago = make_float2(p2, p3);
                if (s + 1 < TSEQ) {
                    const float* xn = xb + (size_t)(s + 1) * 128;
                    p0 = __ldg(xn); p1 = __ldg(xn + 32); p2 = __ldg(xn + 64); p3 = __ldg(xn + 96);
                }
                const float2* hp = h1d + rs * 32;
                const float2* wif = w1if + lane;
                const float2* wgo = w1go + lane;
#pragma unroll
                for (int k = 0; k < 32; k++) {
                    float2 hv = hp[k];               // {h,h} broadcast
                    aif = ffma2(hv, wif[k * 32], aif);
                    ago = ffma2(hv, wgo[k * 32], ago);
                }
                float ig = sigmoid_fast(aif.x);
                float fg = sigmoid_fast(aif.y);
                float gg = tanh_fast(ago.x);
                float og = sigmoid_fast(ago.y);
                cst = fg * cst + ig * gg;
                float h = og * tanh_fast(cst);
                h1d[ws * 32 + lane] = make_float2(h, h);
            }
        } else if (role == 1) {
            if (s >= 1 && s <= TSEQ) {
                float2 acc = b2p[lane];
                const float2* h1p = h1d + rs * 32;
                const float2* wi = w2ip + lane;
#pragma unroll
                for (int k = 0; k < 32; k++)
                    acc = ffma2(h1p[k], wi[k * 32], acc);
                const float2* h2p = h2d + rs * 16;
                const float2* wh = w2hp + lane;
#pragma unroll
                for (int k = 0; k < 16; k++)
                    acc = ffma2(h2p[k], wh[k * 32], acc);
                // lane j<16: acc = {i_j, g_j}; lane 16+u: acc = {f_u, o_u}
                float fpre = __shfl_sync(0xffffffffu, acc.x, (lane & 15) + 16);
                float opre = __shfl_sync(0xffffffffu, acc.y, (lane & 15) + 16);
                if (lane < 16) {
                    float ig = sigmoid_fast(acc.x);
                    float gg = tanh_fast(acc.y);
                    float fg = sigmoid_fast(fpre);
                    float og = sigmoid_fast(opre);
                    cst = fg * cst + ig * gg;
                    float h = og * tanh_fast(cst);
                    h2d[ws * 16 + lane] = make_float2(h, h);
                }
            }
        } else if (role == 2) {
            if (s >= 2 && s <= TSEQ + 1) {
                float2 aa = b3a[lane];
                float2 ab = b3b[lane];
                const float2* h2p = h2d + rs * 16;
                const float2* wa = w3ia + lane;
                const float2* wb = w3ib + lane;
#pragma unroll
                for (int k = 0; k < 16; k++) {
                    float2 hv = h2p[k];
                    aa = ffma2(hv, wa[k * 32], aa);
                    ab = ffma2(hv, wb[k * 32], ab);
                }
                float* pw = pre3s + ws * 128 + lane;
                pw[0]  = aa.x;
                pw[32] = aa.y;
                pw[64] = ab.x;
                pw[96] = ab.y;
            }
        } else {
            if (s >= 3) {
                const float* pr = pre3s + rs * 128 + lane;
                float2 aif = make_float2(pr[0],  pr[32]);
                float2 ago = make_float2(pr[64], pr[96]);
                const float2* h3p = h3d + rs * 32;
                const float2* wif = w3hif + lane;
                const float2* wgo = w3hgo + lane;
#pragma unroll
                for (int k = 0; k < 32; k++) {
                    float2 hv = h3p[k];
                    aif = ffma2(hv, wif[k * 32], aif);
                    ago = ffma2(hv, wgo[k * 32], ago);
                }
                float ig = sigmoid_fast(aif.x);
                float fg = sigmoid_fast(aif.y);
                float gg = tanh_fast(ago.x);
                float og = sigmoid_fast(ago.y);
                cst = fg * cst + ig * gg;
                h3loc = og * tanh_fast(cst);
                h3d[ws * 32 + lane] = make_float2(h3loc, h3loc);
            }
        }
        __syncthreads();
    }

    if (role == 3) out[(size_t)b * 32 + lane] = h3loc;
}

// ---------------- launch ----------------
extern "C" void kernel_launch(void* const* d_in, const int* in_sizes, int n_in,
                              void* d_out, int out_size)
{
    const float* x      = (const float*)d_in[0];
    const float* conv_w = (const float*)d_in[1];
    const float* conv_b = (const float*)d_in[2];
    const float* Wih1   = (const float*)d_in[3];
    const float* Whh1   = (const float*)d_in[4];
    const float* bih1   = (const float*)d_in[5];
    const float* bhh1   = (const float*)d_in[6];
    const float* Wih2   = (const float*)d_in[7];
    const float* Whh2   = (const float*)d_in[8];
    const float* bih2   = (const float*)d_in[9];
    const float* bhh2   = (const float*)d_in[10];
    const float* Wih3   = (const float*)d_in[11];
    const float* Whh3   = (const float*)d_in[12];
    const float* bih3   = (const float*)d_in[13];
    const float* bhh3   = (const float*)d_in[14];
    float* out = (float*)d_out;

    float *conv_p, *xg1_p;
    cudaGetSymbolAddress((void**)&conv_p, g_conv);
    cudaGetSymbolAddress((void**)&xg1_p,  g_xg1);

    cudaFuncSetAttribute(conv2_kernel,     cudaFuncAttributeMaxDynamicSharedMemorySize, CV2_SMEM_BYTES);
    cudaFuncSetAttribute(xg1_mma_kernel,   cudaFuncAttributeMaxDynamicSharedMemorySize, XG_SMEM_BYTES);
    cudaFuncSetAttribute(fused_lstm_kernel, cudaFuncAttributeMaxDynamicSharedMemorySize, FL_SMEM_BYTES);

    // 0) prepack conv weights
    prep_w_kernel<<<320, 256>>>(conv_w);

    // 1) conv (tf32 mma, cp.async pipelined)
    conv2_kernel<<<dim3(4, BATCH), 256, CV2_SMEM_BYTES>>>(x, conv_b);

    // 2) xg1 = seq @ Wih1^T + biases
    xg1_mma_kernel<<<MROWS / 128, 256, XG_SMEM_BYTES>>>(conv_p, Wih1, bih1, bhh1, xg1_p);

    // 3) fused LSTM1+2+3 (smem weights, no spills) -> d_out
    fused_lstm_kernel<<<BATCH, 128, FL_SMEM_BYTES>>>(xg1_p, Whh1, Wih2, Whh2, bih2, bhh2,
                                                     Wih3, Whh3, bih3, bhh3, out);

    (void)in_sizes; (void)n_in; (void)out_size;
}

// round 6
// speedup vs baseline: 1.1680x; 1.1680x over previous
#include <cuda_runtime.h>
#include <cuda_bf16.h>
#include <cstdint>

// Problem constants
#define BATCH   512
#define CIN     128
#define LIN     1024
#define KW      5
#define LOUT    1020
#define TSEQ    1020
#define H1      32
#define H2      16
#define H3      32
#define MROWS   (BATCH * TSEQ)   // 522240

// ---------------- scratch ----------------
__device__ float g_conv[(size_t)BATCH * CIN * LOUT];
__device__ float g_xg1 [(size_t)MROWS * 4 * H1];
__device__ float g_wt  [5 * 128 * 128];   // prepacked conv W: [tap][co][ci], tf32 bits

// ---------------- helpers ----------------
__device__ __forceinline__ float sigmoid_fast(float x) {
    float e = __expf(-x);
    float r; asm("rcp.approx.f32 %0, %1;" : "=f"(r) : "f"(1.f + e));
    return r;
}
__device__ __forceinline__ float tanh_fast(float x) {
    float e = __expf(2.f * x);
    float r; asm("rcp.approx.f32 %0, %1;" : "=f"(r) : "f"(1.f + e));
    return fmaf(-2.f, r, 1.f);
}
__device__ __forceinline__ uint32_t f2tf32(float f) {
    uint32_t r;
    asm("cvt.rna.tf32.f32 %0, %1;" : "=r"(r) : "f"(f));
    return r;
}
__device__ __forceinline__ void mma_tf32(float c[4], const uint32_t a[4], uint32_t b0, uint32_t b1) {
    asm volatile(
        "mma.sync.aligned.m16n8k8.row.col.f32.tf32.tf32.f32 "
        "{%0,%1,%2,%3}, {%4,%5,%6,%7}, {%8,%9}, {%0,%1,%2,%3};"
        : "+f"(c[0]), "+f"(c[1]), "+f"(c[2]), "+f"(c[3])
        : "r"(a[0]), "r"(a[1]), "r"(a[2]), "r"(a[3]), "r"(b0), "r"(b1));
}
__device__ __forceinline__ float2 ffma2(float2 a, float2 b, float2 c) {
    unsigned long long ua, ub, uc, ur;
    ua = *reinterpret_cast<unsigned long long*>(&a);
    ub = *reinterpret_cast<unsigned long long*>(&b);
    uc = *reinterpret_cast<unsigned long long*>(&c);
    asm("fma.rn.f32x2 %0, %1, %2, %3;" : "=l"(ur) : "l"(ua), "l"(ub), "l"(uc));
    return *reinterpret_cast<float2*>(&ur);
}
__device__ __forceinline__ uint32_t smem_u32(const void* p) {
    uint32_t a;
    asm("{ .reg .u64 t; cvta.to.shared.u64 t, %1; cvt.u32.u64 %0, t; }" : "=r"(a) : "l"(p));
    return a;
}
__device__ __forceinline__ void cp16(uint32_t dst, const void* src) {
    asm volatile("cp.async.ca.shared.global [%0], [%1], 16;" :: "r"(dst), "l"(src));
}
__device__ __forceinline__ void cp16n(uint32_t dst, const void* src, int nbytes) {
    asm volatile("cp.async.ca.shared.global [%0], [%1], 16, %2;" :: "r"(dst), "l"(src), "r"(nbytes));
}
#define CTA_BAR() asm volatile("bar.sync 0;" ::: "memory")

// =====================================================================
// W prepack for conv
// =====================================================================
__global__ void prep_w_kernel(const float* __restrict__ w) {
    int i = blockIdx.x * 256 + threadIdx.x;
    if (i < 5 * 128 * 128) {
        int ci = i & 127;
        int r  = i >> 7;
        int co  = r & 127;
        int tap = r >> 7;
        g_wt[i] = __uint_as_float(f2tf32(w[((size_t)co * 128 + ci) * 5 + tap]));
    }
}

// =====================================================================
// conv1d via tf32 MMA, 128co x 256l, cp.async double-buffered
// =====================================================================
#define CV2_WS_ST   12800
#define CV2_XS_ST   (16 * 264)
#define CV2_XS_BASE (2 * CV2_WS_ST)
#define CV2_SMEM_BYTES ((2 * CV2_WS_ST + 2 * CV2_XS_ST) * 4)

__global__ __launch_bounds__(256, 1) void conv2_kernel(
    const float* __restrict__ x, const float* __restrict__ bias)
{
    extern __shared__ float smf[];
    const uint32_t sbase = smem_u32(smf);
    const uint32_t* Su = reinterpret_cast<const uint32_t*>(smf);

    const int b   = blockIdx.y;
    const int lb  = blockIdx.x * 256;
    const int tid = threadIdx.x;
    const int warp = tid >> 5;
    const int lane = tid & 31;
    const int g   = lane >> 2;
    const int t4  = lane & 3;
    const int warp_m = warp >> 1;
    const int warp_n = warp & 1;

    const float* xb = x + (size_t)b * (CIN * LIN);

    float acc[2][16][4];
#pragma unroll
    for (int mi = 0; mi < 2; mi++)
#pragma unroll
        for (int ni = 0; ni < 16; ni++)
#pragma unroll
            for (int e = 0; e < 4; e++) acc[mi][ni][e] = 0.f;

    auto issue_chunk = [&](int c, int s) {
#pragma unroll
        for (int i = 0; i < 10; i++) {
            int v = tid + i * 256;
            int row = v >> 2, q = v & 3;
            uint32_t d = sbase + (uint32_t)(s * CV2_WS_ST + row * 20 + q * 4) * 4;
            cp16(d, g_wt + (size_t)row * 128 + c * 16 + q * 4);
        }
#pragma unroll
        for (int i = 0; i < 5; i++) {
            int v = tid + i * 256;
            if (v < 1040) {
                int row = v / 65, q = v - row * 65;
                int gl = lb + q * 4;
                int nb = (LIN - gl) * 4;
                nb = nb < 0 ? 0 : (nb > 16 ? 16 : nb);
                const float* sp = (nb > 0) ? (xb + (size_t)(c * 16 + row) * LIN + gl) : xb;
                uint32_t d = sbase + (uint32_t)(CV2_XS_BASE + s * CV2_XS_ST + row * 264 + q * 4) * 4;
                cp16n(d, sp, nb);
            }
        }
    };

    for (int c = 0; c < 8; c++) {
        const int s = c & 1;
        if (c == 0) {
            issue_chunk(0, 0);
            asm volatile("cp.async.commit_group;");
        }
        if (c + 1 < 8) {
            issue_chunk(c + 1, s ^ 1);
            asm volatile("cp.async.commit_group;");
            asm volatile("cp.async.wait_group 1;");
        } else {
            asm volatile("cp.async.wait_group 0;");
        }
        __syncthreads();

        const uint32_t* Wst = Su + s * CV2_WS_ST;
        const uint32_t* Xst = Su + CV2_XS_BASE + s * CV2_XS_ST;
#pragma unroll
        for (int tap = 0; tap < 5; tap++) {
#pragma unroll
            for (int ks = 0; ks < 2; ks++) {
                const int k0 = ks * 8;
                uint32_t a[2][4];
#pragma unroll
                for (int mi = 0; mi < 2; mi++) {
                    int row = tap * 128 + warp_m * 32 + mi * 16;
                    a[mi][0] = Wst[(row + g)     * 20 + k0 + t4];
                    a[mi][1] = Wst[(row + 8 + g) * 20 + k0 + t4];
                    a[mi][2] = Wst[(row + g)     * 20 + k0 + t4 + 4];
                    a[mi][3] = Wst[(row + 8 + g) * 20 + k0 + t4 + 4];
                }
#pragma unroll
                for (int ni = 0; ni < 16; ni++) {
                    int col = warp_n * 128 + ni * 8 + g + tap;
                    uint32_t b0 = Xst[(k0 + t4)     * 264 + col];
                    uint32_t b1 = Xst[(k0 + t4 + 4) * 264 + col];
                    mma_tf32(acc[0][ni], a[0], b0, b1);
                    mma_tf32(acc[1][ni], a[1], b0, b1);
                }
            }
        }
        __syncthreads();
    }

    float* ob = g_conv + (size_t)b * (CIN * LOUT);
#pragma unroll
    for (int mi = 0; mi < 2; mi++) {
        int row0 = warp_m * 32 + mi * 16 + g;
        float bv0 = bias[row0];
        float bv1 = bias[row0 + 8];
#pragma unroll
        for (int ni = 0; ni < 16; ni++) {
            int l = lb + warp_n * 128 + ni * 8 + 2 * t4;
            if (l + 1 < LOUT) {
                *reinterpret_cast<float2*>(ob + (size_t)row0 * LOUT + l) =
                    make_float2(acc[mi][ni][0] + bv0, acc[mi][ni][1] + bv0);
                *reinterpret_cast<float2*>(ob + (size_t)(row0 + 8) * LOUT + l) =
                    make_float2(acc[mi][ni][2] + bv1, acc[mi][ni][3] + bv1);
            } else if (l < LOUT) {
                ob[(size_t)row0 * LOUT + l]       = acc[mi][ni][0] + bv0;
                ob[(size_t)(row0 + 8) * LOUT + l] = acc[mi][ni][2] + bv1;
            }
        }
    }
}

// =====================================================================
// xg1 GEMM via tf32 MMA (unchanged)
// =====================================================================
#define XG_STRIDE 132
#define XG_SMEM_BYTES (2 * 128 * XG_STRIDE * 4)

__global__ __launch_bounds__(256) void xg1_mma_kernel(
    const float* __restrict__ A, const float* __restrict__ W,
    const float* __restrict__ b1, const float* __restrict__ b2,
    float* __restrict__ C)
{
    extern __shared__ uint32_t smem_u[];
    uint32_t* As = smem_u;
    uint32_t* Bs = smem_u + 128 * XG_STRIDE;

    const int row0 = blockIdx.x * 128;
    const int tid  = threadIdx.x;
    const int warp = tid >> 5;
    const int lane = tid & 31;
    const int g    = lane >> 2;
    const int t4   = lane & 3;
    const int warp_m = warp >> 1;
    const int warp_n = warp & 1;

    for (int v = tid; v < 128 * 32; v += 256) {
        int r  = v >> 5;
        int k4 = (v & 31) * 4;
        float4 av = *reinterpret_cast<const float4*>(A + (size_t)(row0 + r) * 128 + k4);
        *reinterpret_cast<uint4*>(&As[r * XG_STRIDE + k4]) =
            make_uint4(f2tf32(av.x), f2tf32(av.y), f2tf32(av.z), f2tf32(av.w));
        float4 wv = *reinterpret_cast<const float4*>(W + (size_t)r * 128 + k4);
        *reinterpret_cast<uint4*>(&Bs[r * XG_STRIDE + k4]) =
            make_uint4(f2tf32(wv.x), f2tf32(wv.y), f2tf32(wv.z), f2tf32(wv.w));
    }
    __syncthreads();

    float acc[2][8][4];
#pragma unroll
    for (int mi = 0; mi < 2; mi++)
#pragma unroll
        for (int ni = 0; ni < 8; ni++)
#pragma unroll
            for (int e = 0; e < 4; e++) acc[mi][ni][e] = 0.f;

#pragma unroll
    for (int k0 = 0; k0 < 128; k0 += 8) {
        uint32_t a[2][4];
#pragma unroll
        for (int mi = 0; mi < 2; mi++) {
            int row = warp_m * 32 + mi * 16;
            a[mi][0] = As[(row + g)     * XG_STRIDE + k0 + t4];
            a[mi][1] = As[(row + 8 + g) * XG_STRIDE + k0 + t4];
            a[mi][2] = As[(row + g)     * XG_STRIDE + k0 + t4 + 4];
            a[mi][3] = As[(row + 8 + g) * XG_STRIDE + k0 + t4 + 4];
        }
#pragma unroll
        for (int ni = 0; ni < 8; ni++) {
            int n = warp_n * 64 + ni * 8 + g;
            uint32_t b0 = Bs[n * XG_STRIDE + k0 + t4];
            uint32_t b1 = Bs[n * XG_STRIDE + k0 + t4 + 4];
            mma_tf32(acc[0][ni], a[0], b0, b1);
            mma_tf32(acc[1][ni], a[1], b0, b1);
        }
    }

#pragma unroll
    for (int mi = 0; mi < 2; mi++) {
        int r0 = row0 + warp_m * 32 + mi * 16 + g;
#pragma unroll
        for (int ni = 0; ni < 8; ni++) {
            int n = warp_n * 64 + ni * 8 + 2 * t4;
            float bb0 = b1[n] + b2[n];
            float bb1 = b1[n + 1] + b2[n + 1];
            *reinterpret_cast<float2*>(C + (size_t)r0 * 128 + n) =
                make_float2(acc[mi][ni][0] + bb0, acc[mi][ni][1] + bb1);
            *reinterpret_cast<float2*>(C + (size_t)(r0 + 8) * 128 + n) =
                make_float2(acc[mi][ni][2] + bb0, acc[mi][ni][3] + bb1);
        }
    }
}

// =====================================================================
// Fused LSTM1+2+3: warp-specialized with SEPARATE per-role loops.
// Weights live in REGISTERS inside each role's own loop (disjoint live
// ranges -> no union, no spills, no per-step weight loads).
// Hidden states exchanged through tiny double-buffered smem rings
// (duplicated {h,h} float2 so LDS.64 broadcast feeds ffma2 directly).
// One bar.sync 0 per wall in every role loop (same arrival count).
// =====================================================================
__global__ __launch_bounds__(128) void fused_lstm_kernel(
    const float* __restrict__ xg1,
    const float* __restrict__ Whh1,
    const float* __restrict__ Wih2, const float* __restrict__ Whh2,
    const float* __restrict__ bih2, const float* __restrict__ bhh2,
    const float* __restrict__ Wih3, const float* __restrict__ Whh3,
    const float* __restrict__ bih3, const float* __restrict__ bhh3,
    float* __restrict__ out)
{
    __shared__ __align__(16) float2 h1d[2][32];
    __shared__ __align__(16) float2 h2d[2][16];
    __shared__ __align__(16) float2 h3d[2][32];
    __shared__ __align__(16) float  pre3s[2][128];

    const int tid  = threadIdx.x;
    const int wid  = tid >> 5;
    const int lane = tid & 31;
    const int b    = blockIdx.x;
    const int role = (wid + b) & 3;

    // zero rings (cooperative)
    if (tid < 64) {
        h1d[tid >> 5][tid & 31] = make_float2(0.f, 0.f);
        h3d[tid >> 5][tid & 31] = make_float2(0.f, 0.f);
    } else if (tid < 96) {
        h2d[(tid >> 4) & 1][tid & 15] = make_float2(0.f, 0.f);
    }
    for (int v = tid; v < 256; v += 128) pre3s[v >> 7][v & 127] = 0.f;
    __syncthreads();

    if (role == 0) {
        // ---- L1 recurrence: lane owns h1 unit `lane`
        float2 wif[32], wgo[32];
#pragma unroll
        for (int k = 0; k < 32; k++) {
            wif[k] = make_float2(Whh1[(size_t)lane * 32 + k],        Whh1[(size_t)(32 + lane) * 32 + k]);
            wgo[k] = make_float2(Whh1[(size_t)(64 + lane) * 32 + k], Whh1[(size_t)(96 + lane) * 32 + k]);
        }
        const float* xb = xg1 + (size_t)b * TSEQ * 128 + lane;
        float p0 = xb[0], p1 = xb[32], p2 = xb[64], p3 = xb[96];
        float cst = 0.f;
        for (int s = 0; s < TSEQ + 3; s++) {
            if (s < TSEQ) {
                float2 aif = make_float2(p0, p1);
                float2 ago = make_float2(p2, p3);
                if (s + 1 < TSEQ) {
                    const float* xn = xb + (size_t)(s + 1) * 128;
                    p0 = __ldg(xn); p1 = __ldg(xn + 32); p2 = __ldg(xn + 64); p3 = __ldg(xn + 96);
                }
                const float2* hp = h1d[(s - 1) & 1];
#pragma unroll
                for (int k = 0; k < 32; k++) {
                    float2 hv = hp[k];
                    aif = ffma2(hv, wif[k], aif);
                    ago = ffma2(hv, wgo[k], ago);
                }
                float ig = sigmoid_fast(aif.x);
                float fg = sigmoid_fast(aif.y);
                float gg = tanh_fast(ago.x);
                float og = sigmoid_fast(ago.y);
                cst = fg * cst + ig * gg;
                float h = og * tanh_fast(cst);
                h1d[s & 1][lane] = make_float2(h, h);
            }
            CTA_BAR();
        }
    } else if (role == 1) {
        // ---- L2 gates + recurrence (H2=16; lanes<16 own cells)
        int pa = lane;        // rows 0..31 of Wih2/Whh2: i(0-15), f(16-31)
        int pb = 32 + lane;   // rows 32..63: g(32-47), o(48-63)
        float2 wi[32], wh[16];
#pragma unroll
        for (int k = 0; k < 32; k++)
            wi[k] = make_float2(Wih2[(size_t)pa * 32 + k], Wih2[(size_t)pb * 32 + k]);
#pragma unroll
        for (int k = 0; k < 16; k++)
            wh[k] = make_float2(Whh2[(size_t)pa * 16 + k], Whh2[(size_t)pb * 16 + k]);
        float2 bias2 = make_float2(bih2[pa] + bhh2[pa], bih2[pb] + bhh2[pb]);
        float cst = 0.f;
        for (int s = 0; s < TSEQ + 3; s++) {
            if (s >= 1 && s <= TSEQ) {
                const int rs = (s - 1) & 1;
                float2 acc = bias2;
                const float2* h1p = h1d[rs];
#pragma unroll
                for (int k = 0; k < 32; k++)
                    acc = ffma2(h1p[k], wi[k], acc);
                const float2* h2p = h2d[rs];
#pragma unroll
                for (int k = 0; k < 16; k++)
                    acc = ffma2(h2p[k], wh[k], acc);
                // lane j<16: acc={i_j, g_j}; lane 16+u: acc={f_u, o_u}
                float fpre = __shfl_sync(0xffffffffu, acc.x, (lane & 15) + 16);
                float opre = __shfl_sync(0xffffffffu, acc.y, (lane & 15) + 16);
                if (lane < 16) {
                    float ig = sigmoid_fast(acc.x);
                    float gg = tanh_fast(acc.y);
                    float fg = sigmoid_fast(fpre);
                    float og = sigmoid_fast(opre);
                    cst = fg * cst + ig * gg;
                    float h = og * tanh_fast(cst);
                    h2d[s & 1][lane] = make_float2(h, h);
                }
            }
            CTA_BAR();
        }
    } else if (role == 2) {
        // ---- xg3 matvec: pre3 = Wih3 @ h2 + biases
        float2 wa[16], wb[16];
#pragma unroll
        for (int k = 0; k < 16; k++) {
            wa[k] = make_float2(Wih3[(size_t)lane * 16 + k],        Wih3[(size_t)(32 + lane) * 16 + k]);
            wb[k] = make_float2(Wih3[(size_t)(64 + lane) * 16 + k], Wih3[(size_t)(96 + lane) * 16 + k]);
        }
        float2 b3a = make_float2(bih3[lane] + bhh3[lane],           bih3[32 + lane] + bhh3[32 + lane]);
        float2 b3b = make_float2(bih3[64 + lane] + bhh3[64 + lane], bih3[96 + lane] + bhh3[96 + lane]);
        for (int s = 0; s < TSEQ + 3; s++) {
            if (s >= 2 && s <= TSEQ + 1) {
                const int rs = (s - 1) & 1;
                float2 aa = b3a, ab = b3b;
                const float2* h2p = h2d[rs];
#pragma unroll
                for (int k = 0; k < 16; k++) {
                    float2 hv = h2p[k];
                    aa = ffma2(hv, wa[k], aa);
                    ab = ffma2(hv, wb[k], ab);
                }
                float* pw = &pre3s[s & 1][lane];
                pw[0]  = aa.x;
                pw[32] = aa.y;
                pw[64] = ab.x;
                pw[96] = ab.y;
            }
            CTA_BAR();
        }
    } else {
        // ---- L3 recurrence; writes final h3
        float2 wif[32], wgo[32];
#pragma unroll
        for (int k = 0; k < 32; k++) {
            wif[k] = make_float2(Whh3[(size_t)lane * 32 + k],        Whh3[(size_t)(32 + lane) * 32 + k]);
            wgo[k] = make_float2(Whh3[(size_t)(64 + lane) * 32 + k], Whh3[(size_t)(96 + lane) * 32 + k]);
        }
        float cst = 0.f, h3loc = 0.f;
        for (int s = 0; s < TSEQ + 3; s++) {
            if (s >= 3) {
                const int rs = (s - 1) & 1;
                const float* pr = &pre3s[rs][lane];
                float2 aif = make_float2(pr[0],  pr[32]);
                float2 ago = make_float2(pr[64], pr[96]);
                const float2* h3p = h3d[rs];
#pragma unroll
                for (int k = 0; k < 32; k++) {
                    float2 hv = h3p[k];
                    aif = ffma2(hv, wif[k], aif);
                    ago = ffma2(hv, wgo[k], ago);
                }
                float ig = sigmoid_fast(aif.x);
                float fg = sigmoid_fast(aif.y);
                float gg = tanh_fast(ago.x);
                float og = sigmoid_fast(ago.y);
                cst = fg * cst + ig * gg;
                h3loc = og * tanh_fast(cst);
                h3d[s & 1][lane] = make_float2(h3loc, h3loc);
            }
            CTA_BAR();
        }
        out[(size_t)b * 32 + lane] = h3loc;
    }
}

// ---------------- launch ----------------
extern "C" void kernel_launch(void* const* d_in, const int* in_sizes, int n_in,
                              void* d_out, int out_size)
{
    const float* x      = (const float*)d_in[0];
    const float* conv_w = (const float*)d_in[1];
    const float* conv_b = (const float*)d_in[2];
    const float* Wih1   = (const float*)d_in[3];
    const float* Whh1   = (const float*)d_in[4];
    const float* bih1   = (const float*)d_in[5];
    const float* bhh1   = (const float*)d_in[6];
    const float* Wih2   = (const float*)d_in[7];
    const float* Whh2   = (const float*)d_in[8];
    const float* bih2   = (const float*)d_in[9];
    const float* bhh2   = (const float*)d_in[10];
    const float* Wih3   = (const float*)d_in[11];
    const float* Whh3   = (const float*)d_in[12];
    const float* bih3   = (const float*)d_in[13];
    const float* bhh3   = (const float*)d_in[14];
    float* out = (float*)d_out;

    float *conv_p, *xg1_p;
    cudaGetSymbolAddress((void**)&conv_p, g_conv);
    cudaGetSymbolAddress((void**)&xg1_p,  g_xg1);

    cudaFuncSetAttribute(conv2_kernel,   cudaFuncAttributeMaxDynamicSharedMemorySize, CV2_SMEM_BYTES);
    cudaFuncSetAttribute(xg1_mma_kernel, cudaFuncAttributeMaxDynamicSharedMemorySize, XG_SMEM_BYTES);

    // 0) prepack conv weights
    prep_w_kernel<<<320, 256>>>(conv_w);

    // 1) conv (tf32 mma, cp.async pipelined)
    conv2_kernel<<<dim3(4, BATCH), 256, CV2_SMEM_BYTES>>>(x, conv_b);

    // 2) xg1 = seq @ Wih1^T + biases
    xg1_mma_kernel<<<MROWS / 128, 256, XG_SMEM_BYTES>>>(conv_p, Wih1, bih1, bhh1, xg1_p);

    // 3) fused LSTM1+2+3 (warp-specialized, register weights) -> d_out
    fused_lstm_kernel<<<BATCH, 128>>>(xg1_p, Whh1, Wih2, Whh2, bih2, bhh2,
                                      Wih3, Whh3, bih3, bhh3, out);

    (void)in_sizes; (void)n_in; (void)out_size;
}

// round 7
// speedup vs baseline: 1.3033x; 1.1158x over previous
#include <cuda_runtime.h>
#include <cuda_bf16.h>
#include <cstdint>

// Problem constants
#define BATCH   512
#define CIN     128
#define LIN     1024
#define KW      5
#define LOUT    1020
#define TSEQ    1020
#define H1      32
#define H2      16
#define H3      32
#define MROWS   (BATCH * TSEQ)   // 522240
#define NWALL   (TSEQ / 2 + 3)   // 513

// ---------------- scratch ----------------
__device__ float g_conv[(size_t)BATCH * CIN * LOUT];
__device__ float g_xg1 [(size_t)MROWS * 4 * H1];
__device__ float g_wt  [5 * 128 * 128];

// ---------------- helpers ----------------
__device__ __forceinline__ float sigmoid_fast(float x) {
    float e = __expf(-x);
    float r; asm("rcp.approx.f32 %0, %1;" : "=f"(r) : "f"(1.f + e));
    return r;
}
__device__ __forceinline__ float tanh_fast(float x) {
    float e = __expf(2.f * x);
    float r; asm("rcp.approx.f32 %0, %1;" : "=f"(r) : "f"(1.f + e));
    return fmaf(-2.f, r, 1.f);
}
__device__ __forceinline__ uint32_t f2tf32(float f) {
    uint32_t r;
    asm("cvt.rna.tf32.f32 %0, %1;" : "=r"(r) : "f"(f));
    return r;
}
__device__ __forceinline__ void mma_tf32(float c[4], const uint32_t a[4], uint32_t b0, uint32_t b1) {
    asm volatile(
        "mma.sync.aligned.m16n8k8.row.col.f32.tf32.tf32.f32 "
        "{%0,%1,%2,%3}, {%4,%5,%6,%7}, {%8,%9}, {%0,%1,%2,%3};"
        : "+f"(c[0]), "+f"(c[1]), "+f"(c[2]), "+f"(c[3])
        : "r"(a[0]), "r"(a[1]), "r"(a[2]), "r"(a[3]), "r"(b0), "r"(b1));
}
__device__ __forceinline__ float2 ffma2(float2 a, float2 b, float2 c) {
    unsigned long long ua, ub, uc, ur;
    ua = *reinterpret_cast<unsigned long long*>(&a);
    ub = *reinterpret_cast<unsigned long long*>(&b);
    uc = *reinterpret_cast<unsigned long long*>(&c);
    asm("fma.rn.f32x2 %0, %1, %2, %3;" : "=l"(ur) : "l"(ua), "l"(ub), "l"(uc));
    return *reinterpret_cast<float2*>(&ur);
}
__device__ __forceinline__ uint32_t smem_u32(const void* p) {
    uint32_t a;
    asm("{ .reg .u64 t; cvta.to.shared.u64 t, %1; cvt.u32.u64 %0, t; }" : "=r"(a) : "l"(p));
    return a;
}
__device__ __forceinline__ void cp16(uint32_t dst, const void* src) {
    asm volatile("cp.async.ca.shared.global [%0], [%1], 16;" :: "r"(dst), "l"(src));
}
__device__ __forceinline__ void cp16n(uint32_t dst, const void* src, int nbytes) {
    asm volatile("cp.async.ca.shared.global [%0], [%1], 16, %2;" :: "r"(dst), "l"(src), "r"(nbytes));
}
#define CTA_BAR() asm volatile("bar.sync 0;" ::: "memory")

// H=32 LSTM cell step with 2-way split accumulation chains.
// hp: duplicated {h,h} float2 vector of previous hidden state.
__device__ __forceinline__ float lstm32_step(
    const float2* __restrict__ hp,
    const float2* __restrict__ wif, const float2* __restrict__ wgo,
    float2 aif, float2 ago, float& cst)
{
    float2 aifB = make_float2(0.f, 0.f), agoB = make_float2(0.f, 0.f);
#pragma unroll
    for (int k = 0; k < 16; k++) {
        float2 hv = hp[k];
        aif = ffma2(hv, wif[k], aif);
        ago = ffma2(hv, wgo[k], ago);
    }
#pragma unroll
    for (int k = 16; k < 32; k++) {
        float2 hv = hp[k];
        aifB = ffma2(hv, wif[k], aifB);
        agoB = ffma2(hv, wgo[k], agoB);
    }
    float ig = sigmoid_fast(aif.x + aifB.x);
    float fg = sigmoid_fast(aif.y + aifB.y);
    float gg = tanh_fast(ago.x + agoB.x);
    float og = sigmoid_fast(ago.y + agoB.y);
    cst = fg * cst + ig * gg;
    return og * tanh_fast(cst);
}

// =====================================================================
// W prepack for conv
// =====================================================================
__global__ void prep_w_kernel(const float* __restrict__ w) {
    int i = blockIdx.x * 256 + threadIdx.x;
    if (i < 5 * 128 * 128) {
        int ci = i & 127;
        int r  = i >> 7;
        int co  = r & 127;
        int tap = r >> 7;
        g_wt[i] = __uint_as_float(f2tf32(w[((size_t)co * 128 + ci) * 5 + tap]));
    }
}

// =====================================================================
// conv1d via tf32 MMA (unchanged from R6)
// =====================================================================
#define CV2_WS_ST   12800
#define CV2_XS_ST   (16 * 264)
#define CV2_XS_BASE (2 * CV2_WS_ST)
#define CV2_SMEM_BYTES ((2 * CV2_WS_ST + 2 * CV2_XS_ST) * 4)

__global__ __launch_bounds__(256, 1) void conv2_kernel(
    const float* __restrict__ x, const float* __restrict__ bias)
{
    extern __shared__ float smf[];
    const uint32_t sbase = smem_u32(smf);
    const uint32_t* Su = reinterpret_cast<const uint32_t*>(smf);

    const int b   = blockIdx.y;
    const int lb  = blockIdx.x * 256;
    const int tid = threadIdx.x;
    const int warp = tid >> 5;
    const int lane = tid & 31;
    const int g   = lane >> 2;
    const int t4  = lane & 3;
    const int warp_m = warp >> 1;
    const int warp_n = warp & 1;

    const float* xb = x + (size_t)b * (CIN * LIN);

    float acc[2][16][4];
#pragma unroll
    for (int mi = 0; mi < 2; mi++)
#pragma unroll
        for (int ni = 0; ni < 16; ni++)
#pragma unroll
            for (int e = 0; e < 4; e++) acc[mi][ni][e] = 0.f;

    auto issue_chunk = [&](int c, int s) {
#pragma unroll
        for (int i = 0; i < 10; i++) {
            int v = tid + i * 256;
            int row = v >> 2, q = v & 3;
            uint32_t d = sbase + (uint32_t)(s * CV2_WS_ST + row * 20 + q * 4) * 4;
            cp16(d, g_wt + (size_t)row * 128 + c * 16 + q * 4);
        }
#pragma unroll
        for (int i = 0; i < 5; i++) {
            int v = tid + i * 256;
            if (v < 1040) {
                int row = v / 65, q = v - row * 65;
                int gl = lb + q * 4;
                int nb = (LIN - gl) * 4;
                nb = nb < 0 ? 0 : (nb > 16 ? 16 : nb);
                const float* sp = (nb > 0) ? (xb + (size_t)(c * 16 + row) * LIN + gl) : xb;
                uint32_t d = sbase + (uint32_t)(CV2_XS_BASE + s * CV2_XS_ST + row * 264 + q * 4) * 4;
                cp16n(d, sp, nb);
            }
        }
    };

    for (int c = 0; c < 8; c++) {
        const int s = c & 1;
        if (c == 0) {
            issue_chunk(0, 0);
            asm volatile("cp.async.commit_group;");
        }
        if (c + 1 < 8) {
            issue_chunk(c + 1, s ^ 1);
            asm volatile("cp.async.commit_group;");
            asm volatile("cp.async.wait_group 1;");
        } else {
            asm volatile("cp.async.wait_group 0;");
        }
        __syncthreads();

        const uint32_t* Wst = Su + s * CV2_WS_ST;
        const uint32_t* Xst = Su + CV2_XS_BASE + s * CV2_XS_ST;
#pragma unroll
        for (int tap = 0; tap < 5; tap++) {
#pragma unroll
            for (int ks = 0; ks < 2; ks++) {
                const int k0 = ks * 8;
                uint32_t a[2][4];
#pragma unroll
                for (int mi = 0; mi < 2; mi++) {
                    int row = tap * 128 + warp_m * 32 + mi * 16;
                    a[mi][0] = Wst[(row + g)     * 20 + k0 + t4];
                    a[mi][1] = Wst[(row + 8 + g) * 20 + k0 + t4];
                    a[mi][2] = Wst[(row + g)     * 20 + k0 + t4 + 4];
                    a[mi][3] = Wst[(row + 8 + g) * 20 + k0 + t4 + 4];
                }
#pragma unroll
                for (int ni = 0; ni < 16; ni++) {
                    int col = warp_n * 128 + ni * 8 + g + tap;
                    uint32_t b0 = Xst[(k0 + t4)     * 264 + col];
                    uint32_t b1 = Xst[(k0 + t4 + 4) * 264 + col];
                    mma_tf32(acc[0][ni], a[0], b0, b1);
                    mma_tf32(acc[1][ni], a[1], b0, b1);
                }
            }
        }
        __syncthreads();
    }

    float* ob = g_conv + (size_t)b * (CIN * LOUT);
#pragma unroll
    for (int mi = 0; mi < 2; mi++) {
        int row0 = warp_m * 32 + mi * 16 + g;
        float bv0 = bias[row0];
        float bv1 = bias[row0 + 8];
#pragma unroll
        for (int ni = 0; ni < 16; ni++) {
            int l = lb + warp_n * 128 + ni * 8 + 2 * t4;
            if (l + 1 < LOUT) {
                *reinterpret_cast<float2*>(ob + (size_t)row0 * LOUT + l) =
                    make_float2(acc[mi][ni][0] + bv0, acc[mi][ni][1] + bv0);
                *reinterpret_cast<float2*>(ob + (size_t)(row0 + 8) * LOUT + l) =
                    make_float2(acc[mi][ni][2] + bv1, acc[mi][ni][3] + bv1);
            } else if (l < LOUT) {
                ob[(size_t)row0 * LOUT + l]       = acc[mi][ni][0] + bv0;
                ob[(size_t)(row0 + 8) * LOUT + l] = acc[mi][ni][2] + bv1;
            }
        }
    }
}

// =====================================================================
// xg1 GEMM via tf32 MMA (unchanged)
// =====================================================================
#define XG_STRIDE 132
#define XG_SMEM_BYTES (2 * 128 * XG_STRIDE * 4)

__global__ __launch_bounds__(256) void xg1_mma_kernel(
    const float* __restrict__ A, const float* __restrict__ W,
    const float* __restrict__ b1, const float* __restrict__ b2,
    float* __restrict__ C)
{
    extern __shared__ uint32_t smem_u[];
    uint32_t* As = smem_u;
    uint32_t* Bs = smem_u + 128 * XG_STRIDE;

    const int row0 = blockIdx.x * 128;
    const int tid  = threadIdx.x;
    const int warp = tid >> 5;
    const int lane = tid & 31;
    const int g    = lane >> 2;
    const int t4   = lane & 3;
    const int warp_m = warp >> 1;
    const int warp_n = warp & 1;

    for (int v = tid; v < 128 * 32; v += 256) {
        int r  = v >> 5;
        int k4 = (v & 31) * 4;
        float4 av = *reinterpret_cast<const float4*>(A + (size_t)(row0 + r) * 128 + k4);
        *reinterpret_cast<uint4*>(&As[r * XG_STRIDE + k4]) =
            make_uint4(f2tf32(av.x), f2tf32(av.y), f2tf32(av.z), f2tf32(av.w));
        float4 wv = *reinterpret_cast<const float4*>(W + (size_t)r * 128 + k4);
        *reinterpret_cast<uint4*>(&Bs[r * XG_STRIDE + k4]) =
            make_uint4(f2tf32(wv.x), f2tf32(wv.y), f2tf32(wv.z), f2tf32(wv.w));
    }
    __syncthreads();

    float acc[2][8][4];
#pragma unroll
    for (int mi = 0; mi < 2; mi++)
#pragma unroll
        for (int ni = 0; ni < 8; ni++)
#pragma unroll
            for (int e = 0; e < 4; e++) acc[mi][ni][e] = 0.f;

#pragma unroll
    for (int k0 = 0; k0 < 128; k0 += 8) {
        uint32_t a[2][4];
#pragma unroll
        for (int mi = 0; mi < 2; mi++) {
            int row = warp_m * 32 + mi * 16;
            a[mi][0] = As[(row + g)     * XG_STRIDE + k0 + t4];
            a[mi][1] = As[(row + 8 + g) * XG_STRIDE + k0 + t4];
            a[mi][2] = As[(row + g)     * XG_STRIDE + k0 + t4 + 4];
            a[mi][3] = As[(row + 8 + g) * XG_STRIDE + k0 + t4 + 4];
        }
#pragma unroll
        for (int ni = 0; ni < 8; ni++) {
            int n = warp_n * 64 + ni * 8 + g;
            uint32_t b0 = Bs[n * XG_STRIDE + k0 + t4];
            uint32_t b1 = Bs[n * XG_STRIDE + k0 + t4 + 4];
            mma_tf32(acc[0][ni], a[0], b0, b1);
            mma_tf32(acc[1][ni], a[1], b0, b1);
        }
    }

#pragma unroll
    for (int mi = 0; mi < 2; mi++) {
        int r0 = row0 + warp_m * 32 + mi * 16 + g;
#pragma unroll
        for (int ni = 0; ni < 8; ni++) {
            int n = warp_n * 64 + ni * 8 + 2 * t4;
            float bb0 = b1[n] + b2[n];
            float bb1 = b1[n + 1] + b2[n + 1];
            *reinterpret_cast<float2*>(C + (size_t)r0 * 128 + n) =
                make_float2(acc[mi][ni][0] + bb0, acc[mi][ni][1] + bb1);
            *reinterpret_cast<float2*>(C + (size_t)(r0 + 8) * 128 + n) =
                make_float2(acc[mi][ni][2] + bb0, acc[mi][ni][3] + bb1);
        }
    }
}

// =====================================================================
// Fused LSTM1+2+3: warp-specialized, register weights, TWO timesteps
// per barrier wall (513 walls), 2-way split accumulation chains.
// Rings hold a step pair per wall parity:
//   h1r[2][2][32], h2r[2][2][16], h3r[2][2][32]  (duplicated {h,h} f2)
//   pre3r[2][2][128] floats
// Role schedule (wall m):
//   role0: t = 2m, 2m+1         (m <= 509)
//   role1: t = 2m-2, 2m-1       (1 <= m <= 510)
//   role2: t = 2m-4, 2m-3       (2 <= m <= 511)
//   role3: t = 2m-6, 2m-5       (3 <= m <= 512)
// =====================================================================
__global__ __launch_bounds__(128) void fused_lstm_kernel(
    const float* __restrict__ xg1,
    const float* __restrict__ Whh1,
    const float* __restrict__ Wih2, const float* __restrict__ Whh2,
    const float* __restrict__ bih2, const float* __restrict__ bhh2,
    const float* __restrict__ Wih3, const float* __restrict__ Whh3,
    const float* __restrict__ bih3, const float* __restrict__ bhh3,
    float* __restrict__ out)
{
    __shared__ __align__(16) float2 h1r[2][2][32];
    __shared__ __align__(16) float2 h2r[2][2][16];
    __shared__ __align__(16) float2 h3r[2][2][32];
    __shared__ __align__(16) float  pre3r[2][2][128];

    const int tid  = threadIdx.x;
    const int wid  = tid >> 5;
    const int lane = tid & 31;
    const int b    = blockIdx.x;
    const int role = (wid + b) & 3;

    // zero rings (cooperative): h1r,h2r,h3r contiguous? not guaranteed — zero separately
    for (int v = tid; v < 128; v += 128) h1r[(v >> 6) & 1][(v >> 5) & 1][v & 31] = make_float2(0.f, 0.f);
    if (tid < 64)  h2r[(tid >> 5) & 1][(tid >> 4) & 1][tid & 15] = make_float2(0.f, 0.f);
    for (int v = tid; v < 128; v += 128) h3r[(v >> 6) & 1][(v >> 5) & 1][v & 31] = make_float2(0.f, 0.f);
    for (int v = tid; v < 512; v += 128) pre3r[(v >> 8) & 1][(v >> 7) & 1][v & 127] = 0.f;
    __syncthreads();

    if (role == 0) {
        float2 wif[32], wgo[32];
#pragma unroll
        for (int k = 0; k < 32; k++) {
            wif[k] = make_float2(Whh1[(size_t)lane * 32 + k],        Whh1[(size_t)(32 + lane) * 32 + k]);
            wgo[k] = make_float2(Whh1[(size_t)(64 + lane) * 32 + k], Whh1[(size_t)(96 + lane) * 32 + k]);
        }
        const float* xb = xg1 + (size_t)b * TSEQ * 128 + lane;
        float pA0 = xb[0],   pA1 = xb[32],  pA2 = xb[64],  pA3 = xb[96];
        float pB0 = xb[128], pB1 = xb[160], pB2 = xb[192], pB3 = xb[224];
        float cst = 0.f;
        for (int m = 0; m < NWALL; m++) {
            if (m <= 509) {
                const int rs = (m - 1) & 1, ws = m & 1;
                float2 aifA = make_float2(pA0, pA1), agoA = make_float2(pA2, pA3);
                float2 aifB = make_float2(pB0, pB1), agoB = make_float2(pB2, pB3);
                if (m < 509) {
                    const float* xn = xb + (size_t)(2 * m + 2) * 128;
                    pA0 = __ldg(xn);       pA1 = __ldg(xn + 32);
                    pA2 = __ldg(xn + 64);  pA3 = __ldg(xn + 96);
                    pB0 = __ldg(xn + 128); pB1 = __ldg(xn + 160);
                    pB2 = __ldg(xn + 192); pB3 = __ldg(xn + 224);
                }
                float h = lstm32_step(h1r[rs][1], wif, wgo, aifA, agoA, cst);
                h1r[ws][0][lane] = make_float2(h, h);
                __syncwarp();
                h = lstm32_step(h1r[ws][0], wif, wgo, aifB, agoB, cst);
                h1r[ws][1][lane] = make_float2(h, h);
            }
            CTA_BAR();
        }
    } else if (role == 1) {
        const int pa = lane;        // rows 0..31: i(0-15), f(16-31)
        const int pb = 32 + lane;   // rows 32..63: g(32-47), o(48-63)
        float2 wi[32], wh[16];
#pragma unroll
        for (int k = 0; k < 32; k++)
            wi[k] = make_float2(Wih2[(size_t)pa * 32 + k], Wih2[(size_t)pb * 32 + k]);
#pragma unroll
        for (int k = 0; k < 16; k++)
            wh[k] = make_float2(Whh2[(size_t)pa * 16 + k], Whh2[(size_t)pb * 16 + k]);
        const float2 bias2 = make_float2(bih2[pa] + bhh2[pa], bih2[pb] + bhh2[pb]);
        float cst = 0.f;
        for (int m = 0; m < NWALL; m++) {
            if (m >= 1 && m <= 510) {
                const int rs = (m - 1) & 1, ws = m & 1;
#pragma unroll
                for (int st = 0; st < 2; st++) {
                    float2 acc = bias2, accB = make_float2(0.f, 0.f);
                    const float2* h1p = h1r[rs][st];
#pragma unroll
                    for (int k = 0; k < 16; k++)
                        acc = ffma2(h1p[k], wi[k], acc);
#pragma unroll
                    for (int k = 16; k < 32; k++)
                        accB = ffma2(h1p[k], wi[k], accB);
                    const float2* h2p = (st == 0) ? h2r[rs][1] : h2r[ws][0];
#pragma unroll
                    for (int k = 0; k < 16; k++)
                        accB = ffma2(h2p[k], wh[k], accB);
                    float va = acc.x + accB.x;
                    float vb = acc.y + accB.y;
                    float fpre = __shfl_sync(0xffffffffu, va, (lane & 15) + 16);
                    float opre = __shfl_sync(0xffffffffu, vb, (lane & 15) + 16);
                    if (lane < 16) {
                        float ig = sigmoid_fast(va);
                        float gg = tanh_fast(vb);
                        float fg = sigmoid_fast(fpre);
                        float og = sigmoid_fast(opre);
                        cst = fg * cst + ig * gg;
                        float h = og * tanh_fast(cst);
                        h2r[ws][st][lane] = make_float2(h, h);
                    }
                    __syncwarp();
                }
            }
            CTA_BAR();
        }
    } else if (role == 2) {
        float2 wa[16], wb[16];
#pragma unroll
        for (int k = 0; k < 16; k++) {
            wa[k] = make_float2(Wih3[(size_t)lane * 16 + k],        Wih3[(size_t)(32 + lane) * 16 + k]);
            wb[k] = make_float2(Wih3[(size_t)(64 + lane) * 16 + k], Wih3[(size_t)(96 + lane) * 16 + k]);
        }
        const float2 b3a = make_float2(bih3[lane] + bhh3[lane],           bih3[32 + lane] + bhh3[32 + lane]);
        const float2 b3b = make_float2(bih3[64 + lane] + bhh3[64 + lane], bih3[96 + lane] + bhh3[96 + lane]);
        for (int m = 0; m < NWALL; m++) {
            if (m >= 2 && m <= 511) {
                const int rs = (m - 1) & 1, ws = m & 1;
                // two independent matvecs — interleave for ILP
                float2 aa0 = b3a, ab0 = b3b, aa1 = b3a, ab1 = b3b;
                const float2* h2p0 = h2r[rs][0];
                const float2* h2p1 = h2r[rs][1];
#pragma unroll
                for (int k = 0; k < 16; k++) {
                    float2 hv0 = h2p0[k], hv1 = h2p1[k];
                    aa0 = ffma2(hv0, wa[k], aa0);
                    ab0 = ffma2(hv0, wb[k], ab0);
                    aa1 = ffma2(hv1, wa[k], aa1);
                    ab1 = ffma2(hv1, wb[k], ab1);
                }
                float* p0 = &pre3r[ws][0][lane];
                p0[0] = aa0.x; p0[32] = aa0.y; p0[64] = ab0.x; p0[96] = ab0.y;
                float* p1 = &pre3r[ws][1][lane];
                p1[0] = aa1.x; p1[32] = aa1.y; p1[64] = ab1.x; p1[96] = ab1.y;
            }
            CTA_BAR();
        }
    } else {
        float2 wif[32], wgo[32];
#pragma unroll
        for (int k = 0; k < 32; k++) {
            wif[k] = make_float2(Whh3[(size_t)lane * 32 + k],        Whh3[(size_t)(32 + lane) * 32 + k]);
            wgo[k] = make_float2(Whh3[(size_t)(64 + lane) * 32 + k], Whh3[(size_t)(96 + lane) * 32 + k]);
        }
        float cst = 0.f, h3loc = 0.f;
        for (int m = 0; m < NWALL; m++) {
            if (m >= 3) {
                const int rs = (m - 1) & 1, ws = m & 1;
                const float* prA = &pre3r[rs][0][lane];
                float2 aif = make_float2(prA[0],  prA[32]);
                float2 ago = make_float2(prA[64], prA[96]);
                float h = lstm32_step(h3r[rs][1], wif, wgo, aif, ago, cst);
                h3r[ws][0][lane] = make_float2(h, h);
                __syncwarp();
                const float* prB = &pre3r[rs][1][lane];
                aif = make_float2(prB[0],  prB[32]);
                ago = make_float2(prB[64], prB[96]);
                h3loc = lstm32_step(h3r[ws][0], wif, wgo, aif, ago, cst);
                h3r[ws][1][lane] = make_float2(h3loc, h3loc);
            }
            CTA_BAR();
        }
        out[(size_t)b * 32 + lane] = h3loc;
    }
}

// ---------------- launch ----------------
extern "C" void kernel_launch(void* const* d_in, const int* in_sizes, int n_in,
                              void* d_out, int out_size)
{
    const float* x      = (const float*)d_in[0];
    const float* conv_w = (const float*)d_in[1];
    const float* conv_b = (const float*)d_in[2];
    const float* Wih1   = (const float*)d_in[3];
    const float* Whh1   = (const float*)d_in[4];
    const float* bih1   = (const float*)d_in[5];
    const float* bhh1   = (const float*)d_in[6];
    const float* Wih2   = (const float*)d_in[7];
    const float* Whh2   = (const float*)d_in[8];
    const float* bih2   = (const float*)d_in[9];
    const float* bhh2   = (const float*)d_in[10];
    const float* Wih3   = (const float*)d_in[11];
    const float* Whh3   = (const float*)d_in[12];
    const float* bih3   = (const float*)d_in[13];
    const float* bhh3   = (const float*)d_in[14];
    float* out = (float*)d_out;

    float *conv_p, *xg1_p;
    cudaGetSymbolAddress((void**)&conv_p, g_conv);
    cudaGetSymbolAddress((void**)&xg1_p,  g_xg1);

    cudaFuncSetAttribute(conv2_kernel,   cudaFuncAttributeMaxDynamicSharedMemorySize, CV2_SMEM_BYTES);
    cudaFuncSetAttribute(xg1_mma_kernel, cudaFuncAttributeMaxDynamicSharedMemorySize, XG_SMEM_BYTES);

    // 0) prepack conv weights
    prep_w_kernel<<<320, 256>>>(conv_w);

    // 1) conv (tf32 mma, cp.async pipelined)
    conv2_kernel<<<dim3(4, BATCH), 256, CV2_SMEM_BYTES>>>(x, conv_b);

    // 2) xg1 = seq @ Wih1^T + biases
    xg1_mma_kernel<<<MROWS / 128, 256, XG_SMEM_BYTES>>>(conv_p, Wih1, bih1, bhh1, xg1_p);

    // 3) fused LSTM1+2+3 (2 steps/wall, split chains) -> d_out
    fused_lstm_kernel<<<BATCH, 128>>>(xg1_p, Whh1, Wih2, Whh2, bih2, bhh2,
                                      Wih3, Whh3, bih3, bhh3, out);

    (void)in_sizes; (void)n_in; (void)out_size;
}

// round 8
// speedup vs baseline: 1.3464x; 1.0331x over previous
#include <cuda_runtime.h>
#include <cuda_bf16.h>
#include <cstdint>

// Problem constants
#define BATCH   512
#define CIN     128
#define LIN     1024
#define KW      5
#define LOUT    1020
#define TSEQ    1020
#define H1      32
#define H2      16
#define H3      32
#define MROWS   (BATCH * TSEQ)   // 522240
#define NWALL   (TSEQ / 2 + 3)   // 513

// ---------------- scratch ----------------
__device__ float g_conv[(size_t)BATCH * CIN * LOUT];
__device__ float g_xg1 [(size_t)MROWS * 4 * H1];
__device__ float g_wt  [5 * 128 * 128];

// ---------------- helpers ----------------
__device__ __forceinline__ float sigmoid_fast(float x) {
    float e = __expf(-x);
    float r; asm("rcp.approx.f32 %0, %1;" : "=f"(r) : "f"(1.f + e));
    return r;
}
__device__ __forceinline__ float tanh_fast(float x) {
    float e = __expf(2.f * x);
    float r; asm("rcp.approx.f32 %0, %1;" : "=f"(r) : "f"(1.f + e));
    return fmaf(-2.f, r, 1.f);
}
__device__ __forceinline__ uint32_t f2tf32(float f) {
    uint32_t r;
    asm("cvt.rna.tf32.f32 %0, %1;" : "=r"(r) : "f"(f));
    return r;
}
__device__ __forceinline__ void mma_tf32(float c[4], const uint32_t a[4], uint32_t b0, uint32_t b1) {
    asm volatile(
        "mma.sync.aligned.m16n8k8.row.col.f32.tf32.tf32.f32 "
        "{%0,%1,%2,%3}, {%4,%5,%6,%7}, {%8,%9}, {%0,%1,%2,%3};"
        : "+f"(c[0]), "+f"(c[1]), "+f"(c[2]), "+f"(c[3])
        : "r"(a[0]), "r"(a[1]), "r"(a[2]), "r"(a[3]), "r"(b0), "r"(b1));
}
__device__ __forceinline__ float2 ffma2(float2 a, float2 b, float2 c) {
    unsigned long long ua, ub, uc, ur;
    ua = *reinterpret_cast<unsigned long long*>(&a);
    ub = *reinterpret_cast<unsigned long long*>(&b);
    uc = *reinterpret_cast<unsigned long long*>(&c);
    asm("fma.rn.f32x2 %0, %1, %2, %3;" : "=l"(ur) : "l"(ua), "l"(ub), "l"(uc));
    return *reinterpret_cast<float2*>(&ur);
}
__device__ __forceinline__ uint32_t smem_u32(const void* p) {
    uint32_t a;
    asm("{ .reg .u64 t; cvta.to.shared.u64 t, %1; cvt.u32.u64 %0, t; }" : "=r"(a) : "l"(p));
    return a;
}
__device__ __forceinline__ void cp16(uint32_t dst, const void* src) {
    asm volatile("cp.async.ca.shared.global [%0], [%1], 16;" :: "r"(dst), "l"(src));
}
__device__ __forceinline__ void cp16n(uint32_t dst, const void* src, int nbytes) {
    asm volatile("cp.async.ca.shared.global [%0], [%1], 16, %2;" :: "r"(dst), "l"(src), "r"(nbytes));
}
#define CTA_BAR() asm volatile("bar.sync 0;" ::: "memory")

// H=32 LSTM cell step, 2-way split chains; i/f weights in registers,
// g/o weights streamed from smem (k-major, stride 32 float2, conflict-free).
__device__ __forceinline__ float lstm32_step_sm(
    const float2* __restrict__ hp,
    const float2* __restrict__ wif,        // registers [32]
    const float2* __restrict__ swgo,       // smem base + lane, stride 32
    float2 aif, float2 ago, float& cst)
{
    float2 aifB = make_float2(0.f, 0.f), agoB = make_float2(0.f, 0.f);
#pragma unroll
    for (int k = 0; k < 16; k++) {
        float2 hv = hp[k];
        aif = ffma2(hv, wif[k], aif);
        ago = ffma2(hv, swgo[k * 32], ago);
    }
#pragma unroll
    for (int k = 16; k < 32; k++) {
        float2 hv = hp[k];
        aifB = ffma2(hv, wif[k], aifB);
        agoB = ffma2(hv, swgo[k * 32], agoB);
    }
    float ig = sigmoid_fast(aif.x + aifB.x);
    float fg = sigmoid_fast(aif.y + aifB.y);
    float gg = tanh_fast(ago.x + agoB.x);
    float og = sigmoid_fast(ago.y + agoB.y);
    cst = fg * cst + ig * gg;
    return og * tanh_fast(cst);
}

// =====================================================================
// W prepack for conv
// =====================================================================
__global__ void prep_w_kernel(const float* __restrict__ w) {
    int i = blockIdx.x * 256 + threadIdx.x;
    if (i < 5 * 128 * 128) {
        int ci = i & 127;
        int r  = i >> 7;
        int co  = r & 127;
        int tap = r >> 7;
        g_wt[i] = __uint_as_float(f2tf32(w[((size_t)co * 128 + ci) * 5 + tap]));
    }
}

// =====================================================================
// conv1d via tf32 MMA (unchanged)
// =====================================================================
#define CV2_WS_ST   12800
#define CV2_XS_ST   (16 * 264)
#define CV2_XS_BASE (2 * CV2_WS_ST)
#define CV2_SMEM_BYTES ((2 * CV2_WS_ST + 2 * CV2_XS_ST) * 4)

__global__ __launch_bounds__(256, 1) void conv2_kernel(
    const float* __restrict__ x, const float* __restrict__ bias)
{
    extern __shared__ float smf[];
    const uint32_t sbase = smem_u32(smf);
    const uint32_t* Su = reinterpret_cast<const uint32_t*>(smf);

    const int b   = blockIdx.y;
    const int lb  = blockIdx.x * 256;
    const int tid = threadIdx.x;
    const int warp = tid >> 5;
    const int lane = tid & 31;
    const int g   = lane >> 2;
    const int t4  = lane & 3;
    const int warp_m = warp >> 1;
    const int warp_n = warp & 1;

    const float* xb = x + (size_t)b * (CIN * LIN);

    float acc[2][16][4];
#pragma unroll
    for (int mi = 0; mi < 2; mi++)
#pragma unroll
        for (int ni = 0; ni < 16; ni++)
#pragma unroll
            for (int e = 0; e < 4; e++) acc[mi][ni][e] = 0.f;

    auto issue_chunk = [&](int c, int s) {
#pragma unroll
        for (int i = 0; i < 10; i++) {
            int v = tid + i * 256;
            int row = v >> 2, q = v & 3;
            uint32_t d = sbase + (uint32_t)(s * CV2_WS_ST + row * 20 + q * 4) * 4;
            cp16(d, g_wt + (size_t)row * 128 + c * 16 + q * 4);
        }
#pragma unroll
        for (int i = 0; i < 5; i++) {
            int v = tid + i * 256;
            if (v < 1040) {
                int row = v / 65, q = v - row * 65;
                int gl = lb + q * 4;
                int nb = (LIN - gl) * 4;
                nb = nb < 0 ? 0 : (nb > 16 ? 16 : nb);
                const float* sp = (nb > 0) ? (xb + (size_t)(c * 16 + row) * LIN + gl) : xb;
                uint32_t d = sbase + (uint32_t)(CV2_XS_BASE + s * CV2_XS_ST + row * 264 + q * 4) * 4;
                cp16n(d, sp, nb);
            }
        }
    };

    for (int c = 0; c < 8; c++) {
        const int s = c & 1;
        if (c == 0) {
            issue_chunk(0, 0);
            asm volatile("cp.async.commit_group;");
        }
        if (c + 1 < 8) {
            issue_chunk(c + 1, s ^ 1);
            asm volatile("cp.async.commit_group;");
            asm volatile("cp.async.wait_group 1;");
        } else {
            asm volatile("cp.async.wait_group 0;");
        }
        __syncthreads();

        const uint32_t* Wst = Su + s * CV2_WS_ST;
        const uint32_t* Xst = Su + CV2_XS_BASE + s * CV2_XS_ST;
#pragma unroll
        for (int tap = 0; tap < 5; tap++) {
#pragma unroll
            for (int ks = 0; ks < 2; ks++) {
                const int k0 = ks * 8;
                uint32_t a[2][4];
#pragma unroll
                for (int mi = 0; mi < 2; mi++) {
                    int row = tap * 128 + warp_m * 32 + mi * 16;
                    a[mi][0] = Wst[(row + g)     * 20 + k0 + t4];
                    a[mi][1] = Wst[(row + 8 + g) * 20 + k0 + t4];
                    a[mi][2] = Wst[(row + g)     * 20 + k0 + t4 + 4];
                    a[mi][3] = Wst[(row + 8 + g) * 20 + k0 + t4 + 4];
                }
#pragma unroll
                for (int ni = 0; ni < 16; ni++) {
                    int col = warp_n * 128 + ni * 8 + g + tap;
                    uint32_t b0 = Xst[(k0 + t4)     * 264 + col];
                    uint32_t b1 = Xst[(k0 + t4 + 4) * 264 + col];
                    mma_tf32(acc[0][ni], a[0], b0, b1);
                    mma_tf32(acc[1][ni], a[1], b0, b1);
                }
            }
        }
        __syncthreads();
    }

    float* ob = g_conv + (size_t)b * (CIN * LOUT);
#pragma unroll
    for (int mi = 0; mi < 2; mi++) {
        int row0 = warp_m * 32 + mi * 16 + g;
        float bv0 = bias[row0];
        float bv1 = bias[row0 + 8];
#pragma unroll
        for (int ni = 0; ni < 16; ni++) {
            int l = lb + warp_n * 128 + ni * 8 + 2 * t4;
            if (l + 1 < LOUT) {
                *reinterpret_cast<float2*>(ob + (size_t)row0 * LOUT + l) =
                    make_float2(acc[mi][ni][0] + bv0, acc[mi][ni][1] + bv0);
                *reinterpret_cast<float2*>(ob + (size_t)(row0 + 8) * LOUT + l) =
                    make_float2(acc[mi][ni][2] + bv1, acc[mi][ni][3] + bv1);
            } else if (l < LOUT) {
                ob[(size_t)row0 * LOUT + l]       = acc[mi][ni][0] + bv0;
                ob[(size_t)(row0 + 8) * LOUT + l] = acc[mi][ni][2] + bv1;
            }
        }
    }
}

// =====================================================================
// xg1 GEMM via tf32 MMA (unchanged)
// =====================================================================
#define XG_STRIDE 132
#define XG_SMEM_BYTES (2 * 128 * XG_STRIDE * 4)

__global__ __launch_bounds__(256) void xg1_mma_kernel(
    const float* __restrict__ A, const float* __restrict__ W,
    const float* __restrict__ b1, const float* __restrict__ b2,
    float* __restrict__ C)
{
    extern __shared__ uint32_t smem_u[];
    uint32_t* As = smem_u;
    uint32_t* Bs = smem_u + 128 * XG_STRIDE;

    const int row0 = blockIdx.x * 128;
    const int tid  = threadIdx.x;
    const int warp = tid >> 5;
    const int lane = tid & 31;
    const int g    = lane >> 2;
    const int t4   = lane & 3;
    const int warp_m = warp >> 1;
    const int warp_n = warp & 1;

    for (int v = tid; v < 128 * 32; v += 256) {
        int r  = v >> 5;
        int k4 = (v & 31) * 4;
        float4 av = *reinterpret_cast<const float4*>(A + (size_t)(row0 + r) * 128 + k4);
        *reinterpret_cast<uint4*>(&As[r * XG_STRIDE + k4]) =
            make_uint4(f2tf32(av.x), f2tf32(av.y), f2tf32(av.z), f2tf32(av.w));
        float4 wv = *reinterpret_cast<const float4*>(W + (size_t)r * 128 + k4);
        *reinterpret_cast<uint4*>(&Bs[r * XG_STRIDE + k4]) =
            make_uint4(f2tf32(wv.x), f2tf32(wv.y), f2tf32(wv.z), f2tf32(wv.w));
    }
    __syncthreads();

    float acc[2][8][4];
#pragma unroll
    for (int mi = 0; mi < 2; mi++)
#pragma unroll
        for (int ni = 0; ni < 8; ni++)
#pragma unroll
            for (int e = 0; e < 4; e++) acc[mi][ni][e] = 0.f;

#pragma unroll
    for (int k0 = 0; k0 < 128; k0 += 8) {
        uint32_t a[2][4];
#pragma unroll
        for (int mi = 0; mi < 2; mi++) {
            int row = warp_m * 32 + mi * 16;
            a[mi][0] = As[(row + g)     * XG_STRIDE + k0 + t4];
            a[mi][1] = As[(row + 8 + g) * XG_STRIDE + k0 + t4];
            a[mi][2] = As[(row + g)     * XG_STRIDE + k0 + t4 + 4];
            a[mi][3] = As[(row + 8 + g) * XG_STRIDE + k0 + t4 + 4];
        }
#pragma unroll
        for (int ni = 0; ni < 8; ni++) {
            int n = warp_n * 64 + ni * 8 + g;
            uint32_t b0 = Bs[n * XG_STRIDE + k0 + t4];
            uint32_t b1 = Bs[n * XG_STRIDE + k0 + t4 + 4];
            mma_tf32(acc[0][ni], a[0], b0, b1);
            mma_tf32(acc[1][ni], a[1], b0, b1);
        }
    }

#pragma unroll
    for (int mi = 0; mi < 2; mi++) {
        int r0 = row0 + warp_m * 32 + mi * 16 + g;
#pragma unroll
        for (int ni = 0; ni < 8; ni++) {
            int n = warp_n * 64 + ni * 8 + 2 * t4;
            float bb0 = b1[n] + b2[n];
            float bb1 = b1[n + 1] + b2[n + 1];
            *reinterpret_cast<float2*>(C + (size_t)r0 * 128 + n) =
                make_float2(acc[mi][ni][0] + bb0, acc[mi][ni][1] + bb1);
            *reinterpret_cast<float2*>(C + (size_t)(r0 + 8) * 128 + n) =
                make_float2(acc[mi][ni][2] + bb0, acc[mi][ni][3] + bb1);
        }
    }
}

// =====================================================================
// Fused LSTM1+2+3: warp-specialized, 2 steps/wall, SPLIT weight storage:
// i/f pair in registers, g/o pair (and Whh2) in shared memory so regs
// fit <=128 -> 4 CTAs/SM -> single grid wave.
// =====================================================================
__global__ __launch_bounds__(128, 4) void fused_lstm_kernel(
    const float* __restrict__ xg1,
    const float* __restrict__ Whh1,
    const float* __restrict__ Wih2, const float* __restrict__ Whh2,
    const float* __restrict__ bih2, const float* __restrict__ bhh2,
    const float* __restrict__ Wih3, const float* __restrict__ Whh3,
    const float* __restrict__ bih3, const float* __restrict__ bhh3,
    float* __restrict__ out)
{
    __shared__ __align__(16) float2 sw1go[32][32];   // [k][j] = {Whh1[64+j][k], Whh1[96+j][k]}
    __shared__ __align__(16) float2 sw3go[32][32];   // [k][j] = {Whh3[64+j][k], Whh3[96+j][k]}
    __shared__ __align__(16) float2 sw2h [16][32];   // [k][j] = {Whh2[j][k],    Whh2[32+j][k]}
    __shared__ __align__(16) float2 h1r[2][2][32];
    __shared__ __align__(16) float2 h2r[2][2][16];
    __shared__ __align__(16) float2 h3r[2][2][32];
    __shared__ __align__(16) float  pre3r[2][2][128];

    const int tid  = threadIdx.x;
    const int wid  = tid >> 5;
    const int lane = tid & 31;
    const int b    = blockIdx.x;
    const int role = (wid + b) & 3;

    // cooperative smem weight load
    for (int v = tid; v < 1024; v += 128) {
        int k = v >> 5, j = v & 31;
        sw1go[k][j] = make_float2(Whh1[(size_t)(64 + j) * 32 + k], Whh1[(size_t)(96 + j) * 32 + k]);
        sw3go[k][j] = make_float2(Whh3[(size_t)(64 + j) * 32 + k], Whh3[(size_t)(96 + j) * 32 + k]);
    }
    for (int v = tid; v < 512; v += 128) {
        int k = v >> 5, j = v & 31;
        sw2h[k][j] = make_float2(Whh2[(size_t)j * 16 + k], Whh2[(size_t)(32 + j) * 16 + k]);
    }
    // zero rings
    for (int v = tid; v < 128; v += 128) h1r[(v >> 6) & 1][(v >> 5) & 1][v & 31] = make_float2(0.f, 0.f);
    if (tid < 64)  h2r[(tid >> 5) & 1][(tid >> 4) & 1][tid & 15] = make_float2(0.f, 0.f);
    for (int v = tid; v < 128; v += 128) h3r[(v >> 6) & 1][(v >> 5) & 1][v & 31] = make_float2(0.f, 0.f);
    for (int v = tid; v < 512; v += 128) pre3r[(v >> 8) & 1][(v >> 7) & 1][v & 127] = 0.f;
    __syncthreads();

    if (role == 0) {
        float2 wif[32];
#pragma unroll
        for (int k = 0; k < 32; k++)
            wif[k] = make_float2(Whh1[(size_t)lane * 32 + k], Whh1[(size_t)(32 + lane) * 32 + k]);
        const float2* swgo = &sw1go[0][lane];
        const float* xb = xg1 + (size_t)b * TSEQ * 128 + lane;
        float pA0 = xb[0],   pA1 = xb[32],  pA2 = xb[64],  pA3 = xb[96];
        float pB0 = xb[128], pB1 = xb[160], pB2 = xb[192], pB3 = xb[224];
        float cst = 0.f;
        for (int m = 0; m < NWALL; m++) {
            if (m <= 509) {
                const int rs = (m - 1) & 1, ws = m & 1;
                float2 aifA = make_float2(pA0, pA1), agoA = make_float2(pA2, pA3);
                float2 aifB = make_float2(pB0, pB1), agoB = make_float2(pB2, pB3);
                if (m < 509) {
                    const float* xn = xb + (size_t)(2 * m + 2) * 128;
                    pA0 = __ldg(xn);       pA1 = __ldg(xn + 32);
                    pA2 = __ldg(xn + 64);  pA3 = __ldg(xn + 96);
                    pB0 = __ldg(xn + 128); pB1 = __ldg(xn + 160);
                    pB2 = __ldg(xn + 192); pB3 = __ldg(xn + 224);
                }
                float h = lstm32_step_sm(h1r[rs][1], wif, swgo, aifA, agoA, cst);
                h1r[ws][0][lane] = make_float2(h, h);
                __syncwarp();
                h = lstm32_step_sm(h1r[ws][0], wif, swgo, aifB, agoB, cst);
                h1r[ws][1][lane] = make_float2(h, h);
            }
            CTA_BAR();
        }
    } else if (role == 1) {
        const int pa = lane;
        const int pb = 32 + lane;
        float2 wi[32];
#pragma unroll
        for (int k = 0; k < 32; k++)
            wi[k] = make_float2(Wih2[(size_t)pa * 32 + k], Wih2[(size_t)pb * 32 + k]);
        const float2* swh = &sw2h[0][lane];
        const float2 bias2 = make_float2(bih2[pa] + bhh2[pa], bih2[pb] + bhh2[pb]);
        float cst = 0.f;
        for (int m = 0; m < NWALL; m++) {
            if (m >= 1 && m <= 510) {
                const int rs = (m - 1) & 1, ws = m & 1;
#pragma unroll
                for (int st = 0; st < 2; st++) {
                    float2 acc = bias2, accB = make_float2(0.f, 0.f);
                    const float2* h1p = h1r[rs][st];
#pragma unroll
                    for (int k = 0; k < 16; k++)
                        acc = ffma2(h1p[k], wi[k], acc);
#pragma unroll
                    for (int k = 16; k < 32; k++)
                        accB = ffma2(h1p[k], wi[k], accB);
                    const float2* h2p = (st == 0) ? h2r[rs][1] : h2r[ws][0];
#pragma unroll
                    for (int k = 0; k < 16; k++)
                        accB = ffma2(h2p[k], swh[k * 32], accB);
                    float va = acc.x + accB.x;
                    float vb = acc.y + accB.y;
                    float fpre = __shfl_sync(0xffffffffu, va, (lane & 15) + 16);
                    float opre = __shfl_sync(0xffffffffu, vb, (lane & 15) + 16);
                    if (lane < 16) {
                        float ig = sigmoid_fast(va);
                        float gg = tanh_fast(vb);
                        float fg = sigmoid_fast(fpre);
                        float og = sigmoid_fast(opre);
                        cst = fg * cst + ig * gg;
                        float h = og * tanh_fast(cst);
                        h2r[ws][st][lane] = make_float2(h, h);
                    }
                    __syncwarp();
                }
            }
            CTA_BAR();
        }
    } else if (role == 2) {
        float2 wa[16], wb[16];
#pragma unroll
        for (int k = 0; k < 16; k++) {
            wa[k] = make_float2(Wih3[(size_t)lane * 16 + k],        Wih3[(size_t)(32 + lane) * 16 + k]);
            wb[k] = make_float2(Wih3[(size_t)(64 + lane) * 16 + k], Wih3[(size_t)(96 + lane) * 16 + k]);
        }
        const float2 b3a = make_float2(bih3[lane] + bhh3[lane],           bih3[32 + lane] + bhh3[32 + lane]);
        const float2 b3b = make_float2(bih3[64 + lane] + bhh3[64 + lane], bih3[96 + lane] + bhh3[96 + lane]);
        for (int m = 0; m < NWALL; m++) {
            if (m >= 2 && m <= 511) {
                const int rs = (m - 1) & 1, ws = m & 1;
                float2 aa0 = b3a, ab0 = b3b, aa1 = b3a, ab1 = b3b;
                const float2* h2p0 = h2r[rs][0];
                const float2* h2p1 = h2r[rs][1];
#pragma unroll
                for (int k = 0; k < 16; k++) {
                    float2 hv0 = h2p0[k], hv1 = h2p1[k];
                    aa0 = ffma2(hv0, wa[k], aa0);
                    ab0 = ffma2(hv0, wb[k], ab0);
                    aa1 = ffma2(hv1, wa[k], aa1);
                    ab1 = ffma2(hv1, wb[k], ab1);
                }
                float* p0 = &pre3r[ws][0][lane];
                p0[0] = aa0.x; p0[32] = aa0.y; p0[64] = ab0.x; p0[96] = ab0.y;
                float* p1 = &pre3r[ws][1][lane];
                p1[0] = aa1.x; p1[32] = aa1.y; p1[64] = ab1.x; p1[96] = ab1.y;
            }
            CTA_BAR();
        }
    } else {
        float2 wif[32];
#pragma unroll
        for (int k = 0; k < 32; k++)
            wif[k] = make_float2(Whh3[(size_t)lane * 32 + k], Whh3[(size_t)(32 + lane) * 32 + k]);
        const float2* swgo = &sw3go[0][lane];
        float cst = 0.f, h3loc = 0.f;
        for (int m = 0; m < NWALL; m++) {
            if (m >= 3) {
                const int rs = (m - 1) & 1, ws = m & 1;
                const float* prA = &pre3r[rs][0][lane];
                float2 aif = make_float2(prA[0],  prA[32]);
                float2 ago = make_float2(prA[64], prA[96]);
                float h = lstm32_step_sm(h3r[rs][1], wif, swgo, aif, ago, cst);
                h3r[ws][0][lane] = make_float2(h, h);
                __syncwarp();
                const float* prB = &pre3r[rs][1][lane];
                aif = make_float2(prB[0],  prB[32]);
                ago = make_float2(prB[64], prB[96]);
                h3loc = lstm32_step_sm(h3r[ws][0], wif, swgo, aif, ago, cst);
                h3r[ws][1][lane] = make_float2(h3loc, h3loc);
            }
            CTA_BAR();
        }
        out[(size_t)b * 32 + lane] = h3loc;
    }
}

// ---------------- launch ----------------
extern "C" void kernel_launch(void* const* d_in, const int* in_sizes, int n_in,
                              void* d_out, int out_size)
{
    const float* x      = (const float*)d_in[0];
    const float* conv_w = (const float*)d_in[1];
    const float* conv_b = (const float*)d_in[2];
    const float* Wih1   = (const float*)d_in[3];
    const float* Whh1   = (const float*)d_in[4];
    const float* bih1   = (const float*)d_in[5];
    const float* bhh1   = (const float*)d_in[6];
    const float* Wih2   = (const float*)d_in[7];
    const float* Whh2   = (const float*)d_in[8];
    const float* bih2   = (const float*)d_in[9];
    const float* bhh2   = (const float*)d_in[10];
    const float* Wih3   = (const float*)d_in[11];
    const float* Whh3   = (const float*)d_in[12];
    const float* bih3   = (const float*)d_in[13];
    const float* bhh3   = (const float*)d_in[14];
    float* out = (float*)d_out;

    float *conv_p, *xg1_p;
    cudaGetSymbolAddress((void**)&conv_p, g_conv);
    cudaGetSymbolAddress((void**)&xg1_p,  g_xg1);

    cudaFuncSetAttribute(conv2_kernel,   cudaFuncAttributeMaxDynamicSharedMemorySize, CV2_SMEM_BYTES);
    cudaFuncSetAttribute(xg1_mma_kernel, cudaFuncAttributeMaxDynamicSharedMemorySize, XG_SMEM_BYTES);

    // 0) prepack conv weights
    prep_w_kernel<<<320, 256>>>(conv_w);

    // 1) conv (tf32 mma, cp.async pipelined)
    conv2_kernel<<<dim3(4, BATCH), 256, CV2_SMEM_BYTES>>>(x, conv_b);

    // 2) xg1 = seq @ Wih1^T + biases
    xg1_mma_kernel<<<MROWS / 128, 256, XG_SMEM_BYTES>>>(conv_p, Wih1, bih1, bhh1, xg1_p);

    // 3) fused LSTM1+2+3 (4 CTAs/SM, single wave) -> d_out
    fused_lstm_kernel<<<BATCH, 128>>>(xg1_p, Whh1, Wih2, Whh2, bih2, bhh2,
                                      Wih3, Whh3, bih3, bhh3, out);

    (void)in_sizes; (void)n_in; (void)out_size;
}

// round 9
// speedup vs baseline: 1.3649x; 1.0138x over previous
#include <cuda_runtime.h>
#include <cuda_bf16.h>
#include <cstdint>

// Problem constants
#define BATCH   512
#define CIN     128
#define LIN     1024
#define KW      5
#define LOUT    1020
#define TSEQ    1020
#define H1      32
#define H2      16
#define H3      32
#define MROWS   (BATCH * TSEQ)   // 522240
#define NWALL   (TSEQ / 2 + 3)   // 513

// ---------------- scratch ----------------
__device__ float g_conv[(size_t)BATCH * CIN * LOUT];
__device__ float g_xg1 [(size_t)MROWS * 4 * H1];
__device__ float g_wt  [5 * 128 * 128];

// ---------------- helpers ----------------
__device__ __forceinline__ float sigmoid_fast(float x) {
    float e = __expf(-x);
    float r; asm("rcp.approx.f32 %0, %1;" : "=f"(r) : "f"(1.f + e));
    return r;
}
__device__ __forceinline__ float tanh_fast(float x) {
    float e = __expf(2.f * x);
    float r; asm("rcp.approx.f32 %0, %1;" : "=f"(r) : "f"(1.f + e));
    return fmaf(-2.f, r, 1.f);
}
__device__ __forceinline__ uint32_t f2tf32(float f) {
    uint32_t r;
    asm("cvt.rna.tf32.f32 %0, %1;" : "=r"(r) : "f"(f));
    return r;
}
__device__ __forceinline__ void mma_tf32(float c[4], const uint32_t a[4], uint32_t b0, uint32_t b1) {
    asm volatile(
        "mma.sync.aligned.m16n8k8.row.col.f32.tf32.tf32.f32 "
        "{%0,%1,%2,%3}, {%4,%5,%6,%7}, {%8,%9}, {%0,%1,%2,%3};"
        : "+f"(c[0]), "+f"(c[1]), "+f"(c[2]), "+f"(c[3])
        : "r"(a[0]), "r"(a[1]), "r"(a[2]), "r"(a[3]), "r"(b0), "r"(b1));
}
__device__ __forceinline__ float2 ffma2(float2 a, float2 b, float2 c) {
    unsigned long long ua, ub, uc, ur;
    ua = *reinterpret_cast<unsigned long long*>(&a);
    ub = *reinterpret_cast<unsigned long long*>(&b);
    uc = *reinterpret_cast<unsigned long long*>(&c);
    asm("fma.rn.f32x2 %0, %1, %2, %3;" : "=l"(ur) : "l"(ua), "l"(ub), "l"(uc));
    return *reinterpret_cast<float2*>(&ur);
}
__device__ __forceinline__ uint32_t smem_u32(const void* p) {
    uint32_t a;
    asm("{ .reg .u64 t; cvta.to.shared.u64 t, %1; cvt.u32.u64 %0, t; }" : "=r"(a) : "l"(p));
    return a;
}
__device__ __forceinline__ void cp16(uint32_t dst, const void* src) {
    asm volatile("cp.async.ca.shared.global [%0], [%1], 16;" :: "r"(dst), "l"(src));
}
__device__ __forceinline__ void cp16n(uint32_t dst, const void* src, int nbytes) {
    asm volatile("cp.async.ca.shared.global [%0], [%1], 16, %2;" :: "r"(dst), "l"(src), "r"(nbytes));
}
#define CTA_BAR() asm volatile("bar.sync 0;" ::: "memory")

// H=32 LSTM cell step, 2-way split chains; i/f weights in registers,
// g/o weights streamed from smem.
__device__ __forceinline__ float lstm32_step_sm(
    const float2* __restrict__ hp,
    const float2* __restrict__ wif,
    const float2* __restrict__ swgo,
    float2 aif, float2 ago, float& cst)
{
    float2 aifB = make_float2(0.f, 0.f), agoB = make_float2(0.f, 0.f);
#pragma unroll
    for (int k = 0; k < 16; k++) {
        float2 hv = hp[k];
        aif = ffma2(hv, wif[k], aif);
        ago = ffma2(hv, swgo[k * 32], ago);
    }
#pragma unroll
    for (int k = 16; k < 32; k++) {
        float2 hv = hp[k];
        aifB = ffma2(hv, wif[k], aifB);
        agoB = ffma2(hv, swgo[k * 32], agoB);
    }
    float ig = sigmoid_fast(aif.x + aifB.x);
    float fg = sigmoid_fast(aif.y + aifB.y);
    float gg = tanh_fast(ago.x + agoB.x);
    float og = sigmoid_fast(ago.y + agoB.y);
    cst = fg * cst + ig * gg;
    return og * tanh_fast(cst);
}

// =====================================================================
// W prepack for conv
// =====================================================================
__global__ void prep_w_kernel(const float* __restrict__ w) {
    int i = blockIdx.x * 256 + threadIdx.x;
    if (i < 5 * 128 * 128) {
        int ci = i & 127;
        int r  = i >> 7;
        int co  = r & 127;
        int tap = r >> 7;
        g_wt[i] = __uint_as_float(f2tf32(w[((size_t)co * 128 + ci) * 5 + tap]));
    }
}

// =====================================================================
// conv1d via tf32 MMA, 64co x 256l tile, 2 CTAs/SM, cp.async 2-stage.
// grid (4, 512, 2), block 256 (8 warps: warp_m in [0,2), warp_n in [0,4)).
// smem: Ws[2][5*64*20] + Xs[2][16*264] = 84992 B
// =====================================================================
#define CV3_WS_ST   6400           // floats per W stage (5*64*20)
#define CV3_XS_ST   (16 * 264)
#define CV3_XS_BASE (2 * CV3_WS_ST)
#define CV3_SMEM_BYTES ((2 * CV3_WS_ST + 2 * CV3_XS_ST) * 4)   // 84992

__global__ __launch_bounds__(256, 2) void conv3_kernel(
    const float* __restrict__ x, const float* __restrict__ bias)
{
    extern __shared__ float smf[];
    const uint32_t sbase = smem_u32(smf);
    const uint32_t* Su = reinterpret_cast<const uint32_t*>(smf);

    const int b   = blockIdx.y;
    const int lb  = blockIdx.x * 256;
    const int co0 = blockIdx.z * 64;
    const int tid = threadIdx.x;
    const int warp = tid >> 5;
    const int lane = tid & 31;
    const int g   = lane >> 2;
    const int t4  = lane & 3;
    const int warp_m = warp >> 2;   // 0..1 : 32 co per warp
    const int warp_n = warp & 3;    // 0..3 : 64 l per warp

    const float* xb = x + (size_t)b * (CIN * LIN);

    float acc[2][8][4];
#pragma unroll
    for (int mi = 0; mi < 2; mi++)
#pragma unroll
        for (int ni = 0; ni < 8; ni++)
#pragma unroll
            for (int e = 0; e < 4; e++) acc[mi][ni][e] = 0.f;

    auto issue_chunk = [&](int c, int s) {
        // W: 320 rows (tap*64+co_local) x 16 floats -> stride-20 smem rows
#pragma unroll
        for (int i = 0; i < 5; i++) {
            int v = tid + i * 256;            // 0..1279
            int row = v >> 2, q = v & 3;
            int tap = row >> 6, col = row & 63;
            uint32_t d = sbase + (uint32_t)(s * CV3_WS_ST + row * 20 + q * 4) * 4;
            cp16(d, g_wt + (size_t)(tap * 128 + co0 + col) * 128 + c * 16 + q * 4);
        }
        // X: 16 rows x 260 floats (65 x 16B), tail zero-filled
#pragma unroll
        for (int i = 0; i < 5; i++) {
            int v = tid + i * 256;
            if (v < 1040) {
                int row = v / 65, q = v - row * 65;
                int gl = lb + q * 4;
                int nb = (LIN - gl) * 4;
                nb = nb < 0 ? 0 : (nb > 16 ? 16 : nb);
                const float* sp = (nb > 0) ? (xb + (size_t)(c * 16 + row) * LIN + gl) : xb;
                uint32_t d = sbase + (uint32_t)(CV3_XS_BASE + s * CV3_XS_ST + row * 264 + q * 4) * 4;
                cp16n(d, sp, nb);
            }
        }
    };

    for (int c = 0; c < 8; c++) {
        const int s = c & 1;
        if (c == 0) {
            issue_chunk(0, 0);
            asm volatile("cp.async.commit_group;");
        }
        if (c + 1 < 8) {
            issue_chunk(c + 1, s ^ 1);
            asm volatile("cp.async.commit_group;");
            asm volatile("cp.async.wait_group 1;");
        } else {
            asm volatile("cp.async.wait_group 0;");
        }
        __syncthreads();

        const uint32_t* Wst = Su + s * CV3_WS_ST;
        const uint32_t* Xst = Su + CV3_XS_BASE + s * CV3_XS_ST;
#pragma unroll
        for (int tap = 0; tap < 5; tap++) {
#pragma unroll
            for (int ks = 0; ks < 2; ks++) {
                const int k0 = ks * 8;
                uint32_t a[2][4];
#pragma unroll
                for (int mi = 0; mi < 2; mi++) {
                    int row = tap * 64 + warp_m * 32 + mi * 16;
                    a[mi][0] = Wst[(row + g)     * 20 + k0 + t4];
                    a[mi][1] = Wst[(row + 8 + g) * 20 + k0 + t4];
                    a[mi][2] = Wst[(row + g)     * 20 + k0 + t4 + 4];
                    a[mi][3] = Wst[(row + 8 + g) * 20 + k0 + t4 + 4];
                }
#pragma unroll
                for (int ni = 0; ni < 8; ni++) {
                    int col = warp_n * 64 + ni * 8 + g + tap;
                    uint32_t b0 = Xst[(k0 + t4)     * 264 + col];
                    uint32_t b1 = Xst[(k0 + t4 + 4) * 264 + col];
                    mma_tf32(acc[0][ni], a[0], b0, b1);
                    mma_tf32(acc[1][ni], a[1], b0, b1);
                }
            }
        }
        __syncthreads();
    }

    float* ob = g_conv + (size_t)b * (CIN * LOUT);
#pragma unroll
    for (int mi = 0; mi < 2; mi++) {
        int row0 = co0 + warp_m * 32 + mi * 16 + g;
        float bv0 = bias[row0];
        float bv1 = bias[row0 + 8];
#pragma unroll
        for (int ni = 0; ni < 8; ni++) {
            int l = lb + warp_n * 64 + ni * 8 + 2 * t4;
            if (l + 1 < LOUT) {
                *reinterpret_cast<float2*>(ob + (size_t)row0 * LOUT + l) =
                    make_float2(acc[mi][ni][0] + bv0, acc[mi][ni][1] + bv0);
                *reinterpret_cast<float2*>(ob + (size_t)(row0 + 8) * LOUT + l) =
                    make_float2(acc[mi][ni][2] + bv1, acc[mi][ni][3] + bv1);
            } else if (l < LOUT) {
                ob[(size_t)row0 * LOUT + l]       = acc[mi][ni][0] + bv0;
                ob[(size_t)(row0 + 8) * LOUT + l] = acc[mi][ni][2] + bv1;
            }
        }
    }
}

// =====================================================================
// xg1 GEMM via tf32 MMA, 64-row tiles, 2 CTAs/SM.
// grid 8160, block 256 (8 warps: warp_m in [0,4), warp_n in [0,2)).
// smem: As[64][132] + Bs[128][132] = 101376 B
// =====================================================================
#define XGB_STRIDE 132
#define XGB_SMEM_BYTES ((64 + 128) * XGB_STRIDE * 4)   // 101376

__global__ __launch_bounds__(256, 2) void xg1b_kernel(
    const float* __restrict__ A, const float* __restrict__ W,
    const float* __restrict__ b1, const float* __restrict__ b2,
    float* __restrict__ C)
{
    extern __shared__ uint32_t smem_u[];
    uint32_t* As = smem_u;                     // [64][132]
    uint32_t* Bs = smem_u + 64 * XGB_STRIDE;   // [128][132]

    const int row0 = blockIdx.x * 64;
    const int tid  = threadIdx.x;
    const int warp = tid >> 5;
    const int lane = tid & 31;
    const int g    = lane >> 2;
    const int t4   = lane & 3;
    const int warp_m = warp >> 1;   // 0..3 : 16 rows per warp
    const int warp_n = warp & 1;    // 0..1 : 64 cols per warp

    for (int v = tid; v < 64 * 32; v += 256) {
        int r  = v >> 5;
        int k4 = (v & 31) * 4;
        float4 av = *reinterpret_cast<const float4*>(A + (size_t)(row0 + r) * 128 + k4);
        *reinterpret_cast<uint4*>(&As[r * XGB_STRIDE + k4]) =
            make_uint4(f2tf32(av.x), f2tf32(av.y), f2tf32(av.z), f2tf32(av.w));
    }
    for (int v = tid; v < 128 * 32; v += 256) {
        int r  = v >> 5;
        int k4 = (v & 31) * 4;
        float4 wv = *reinterpret_cast<const float4*>(W + (size_t)r * 128 + k4);
        *reinterpret_cast<uint4*>(&Bs[r * XGB_STRIDE + k4]) =
            make_uint4(f2tf32(wv.x), f2tf32(wv.y), f2tf32(wv.z), f2tf32(wv.w));
    }
    __syncthreads();

    float acc[8][4];
#pragma unroll
    for (int ni = 0; ni < 8; ni++)
#pragma unroll
        for (int e = 0; e < 4; e++) acc[ni][e] = 0.f;

#pragma unroll
    for (int k0 = 0; k0 < 128; k0 += 8) {
        uint32_t a[4];
        int row = warp_m * 16;
        a[0] = As[(row + g)     * XGB_STRIDE + k0 + t4];
        a[1] = As[(row + 8 + g) * XGB_STRIDE + k0 + t4];
        a[2] = As[(row + g)     * XGB_STRIDE + k0 + t4 + 4];
        a[3] = As[(row + 8 + g) * XGB_STRIDE + k0 + t4 + 4];
#pragma unroll
        for (int ni = 0; ni < 8; ni++) {
            int n = warp_n * 64 + ni * 8 + g;
            uint32_t b0 = Bs[n * XGB_STRIDE + k0 + t4];
            uint32_t b1 = Bs[n * XGB_STRIDE + k0 + t4 + 4];
            mma_tf32(acc[ni], a, b0, b1);
        }
    }

    int r0 = row0 + warp_m * 16 + g;
#pragma unroll
    for (int ni = 0; ni < 8; ni++) {
        int n = warp_n * 64 + ni * 8 + 2 * t4;
        float bb0 = b1[n] + b2[n];
        float bb1 = b1[n + 1] + b2[n + 1];
        *reinterpret_cast<float2*>(C + (size_t)r0 * 128 + n) =
            make_float2(acc[ni][0] + bb0, acc[ni][1] + bb1);
        *reinterpret_cast<float2*>(C + (size_t)(r0 + 8) * 128 + n) =
            make_float2(acc[ni][2] + bb0, acc[ni][3] + bb1);
    }
}

// =====================================================================
// Fused LSTM1+2+3 (unchanged from R8): warp-specialized, 2 steps/wall,
// split weight storage (i/f regs, g/o smem), 4 CTAs/SM.
// =====================================================================
__global__ __launch_bounds__(128, 4) void fused_lstm_kernel(
    const float* __restrict__ xg1,
    const float* __restrict__ Whh1,
    const float* __restrict__ Wih2, const float* __restrict__ Whh2,
    const float* __restrict__ bih2, const float* __restrict__ bhh2,
    const float* __restrict__ Wih3, const float* __restrict__ Whh3,
    const float* __restrict__ bih3, const float* __restrict__ bhh3,
    float* __restrict__ out)
{
    __shared__ __align__(16) float2 sw1go[32][32];
    __shared__ __align__(16) float2 sw3go[32][32];
    __shared__ __align__(16) float2 sw2h [16][32];
    __shared__ __align__(16) float2 h1r[2][2][32];
    __shared__ __align__(16) float2 h2r[2][2][16];
    __shared__ __align__(16) float2 h3r[2][2][32];
    __shared__ __align__(16) float  pre3r[2][2][128];

    const int tid  = threadIdx.x;
    const int wid  = tid >> 5;
    const int lane = tid & 31;
    const int b    = blockIdx.x;
    const int role = (wid + b) & 3;

    for (int v = tid; v < 1024; v += 128) {
        int k = v >> 5, j = v & 31;
        sw1go[k][j] = make_float2(Whh1[(size_t)(64 + j) * 32 + k], Whh1[(size_t)(96 + j) * 32 + k]);
        sw3go[k][j] = make_float2(Whh3[(size_t)(64 + j) * 32 + k], Whh3[(size_t)(96 + j) * 32 + k]);
    }
    for (int v = tid; v < 512; v += 128) {
        int k = v >> 5, j = v & 31;
        sw2h[k][j] = make_float2(Whh2[(size_t)j * 16 + k], Whh2[(size_t)(32 + j) * 16 + k]);
    }
    for (int v = tid; v < 128; v += 128) h1r[(v >> 6) & 1][(v >> 5) & 1][v & 31] = make_float2(0.f, 0.f);
    if (tid < 64)  h2r[(tid >> 5) & 1][(tid >> 4) & 1][tid & 15] = make_float2(0.f, 0.f);
    for (int v = tid; v < 128; v += 128) h3r[(v >> 6) & 1][(v >> 5) & 1][v & 31] = make_float2(0.f, 0.f);
    for (int v = tid; v < 512; v += 128) pre3r[(v >> 8) & 1][(v >> 7) & 1][v & 127] = 0.f;
    __syncthreads();

    if (role == 0) {
        float2 wif[32];
#pragma unroll
        for (int k = 0; k < 32; k++)
            wif[k] = make_float2(Whh1[(size_t)lane * 32 + k], Whh1[(size_t)(32 + lane) * 32 + k]);
        const float2* swgo = &sw1go[0][lane];
        const float* xb = xg1 + (size_t)b * TSEQ * 128 + lane;
        float pA0 = xb[0],   pA1 = xb[32],  pA2 = xb[64],  pA3 = xb[96];
        float pB0 = xb[128], pB1 = xb[160], pB2 = xb[192], pB3 = xb[224];
        float cst = 0.f;
        for (int m = 0; m < NWALL; m++) {
            if (m <= 509) {
                const int rs = (m - 1) & 1, ws = m & 1;
                float2 aifA = make_float2(pA0, pA1), agoA = make_float2(pA2, pA3);
                float2 aifB = make_float2(pB0, pB1), agoB = make_float2(pB2, pB3);
                if (m < 509) {
                    const float* xn = xb + (size_t)(2 * m + 2) * 128;
                    pA0 = __ldg(xn);       pA1 = __ldg(xn + 32);
                    pA2 = __ldg(xn + 64);  pA3 = __ldg(xn + 96);
                    pB0 = __ldg(xn + 128); pB1 = __ldg(xn + 160);
                    pB2 = __ldg(xn + 192); pB3 = __ldg(xn + 224);
                }
                float h = lstm32_step_sm(h1r[rs][1], wif, swgo, aifA, agoA, cst);
                h1r[ws][0][lane] = make_float2(h, h);
                __syncwarp();
                h = lstm32_step_sm(h1r[ws][0], wif, swgo, aifB, agoB, cst);
                h1r[ws][1][lane] = make_float2(h, h);
            }
            CTA_BAR();
        }
    } else if (role == 1) {
        const int pa = lane;
        const int pb = 32 + lane;
        float2 wi[32];
#pragma unroll
        for (int k = 0; k < 32; k++)
            wi[k] = make_float2(Wih2[(size_t)pa * 32 + k], Wih2[(size_t)pb * 32 + k]);
        const float2* swh = &sw2h[0][lane];
        const float2 bias2 = make_float2(bih2[pa] + bhh2[pa], bih2[pb] + bhh2[pb]);
        float cst = 0.f;
        for (int m = 0; m < NWALL; m++) {
            if (m >= 1 && m <= 510) {
                const int rs = (m - 1) & 1, ws = m & 1;
#pragma unroll
                for (int st = 0; st < 2; st++) {
                    float2 acc = bias2, accB = make_float2(0.f, 0.f);
                    const float2* h1p = h1r[rs][st];
#pragma unroll
                    for (int k = 0; k < 16; k++)
                        acc = ffma2(h1p[k], wi[k], acc);
#pragma unroll
                    for (int k = 16; k < 32; k++)
                        accB = ffma2(h1p[k], wi[k], accB);
                    const float2* h2p = (st == 0) ? h2r[rs][1] : h2r[ws][0];
#pragma unroll
                    for (int k = 0; k < 16; k++)
                        accB = ffma2(h2p[k], swh[k * 32], accB);
                    float va = acc.x + accB.x;
                    float vb = acc.y + accB.y;
                    float fpre = __shfl_sync(0xffffffffu, va, (lane & 15) + 16);
                    float opre = __shfl_sync(0xffffffffu, vb, (lane & 15) + 16);
                    if (lane < 16) {
                        float ig = sigmoid_fast(va);
                        float gg = tanh_fast(vb);
                        float fg = sigmoid_fast(fpre);
                        float og = sigmoid_fast(opre);
                        cst = fg * cst + ig * gg;
                        float h = og * tanh_fast(cst);
                        h2r[ws][st][lane] = make_float2(h, h);
                    }
                    __syncwarp();
                }
            }
            CTA_BAR();
        }
    } else if (role == 2) {
        float2 wa[16], wb[16];
#pragma unroll
        for (int k = 0; k < 16; k++) {
            wa[k] = make_float2(Wih3[(size_t)lane * 16 + k],        Wih3[(size_t)(32 + lane) * 16 + k]);
            wb[k] = make_float2(Wih3[(size_t)(64 + lane) * 16 + k], Wih3[(size_t)(96 + lane) * 16 + k]);
        }
        const float2 b3a = make_float2(bih3[lane] + bhh3[lane],           bih3[32 + lane] + bhh3[32 + lane]);
        const float2 b3b = make_float2(bih3[64 + lane] + bhh3[64 + lane], bih3[96 + lane] + bhh3[96 + lane]);
        for (int m = 0; m < NWALL; m++) {
            if (m >= 2 && m <= 511) {
                const int rs = (m - 1) & 1, ws = m & 1;
                float2 aa0 = b3a, ab0 = b3b, aa1 = b3a, ab1 = b3b;
                const float2* h2p0 = h2r[rs][0];
                const float2* h2p1 = h2r[rs][1];
#pragma unroll
                for (int k = 0; k < 16; k++) {
                    float2 hv0 = h2p0[k], hv1 = h2p1[k];
                    aa0 = ffma2(hv0, wa[k], aa0);
                    ab0 = ffma2(hv0, wb[k], ab0);
                    aa1 = ffma2(hv1, wa[k], aa1);
                    ab1 = ffma2(hv1, wb[k], ab1);
                }
                float* p0 = &pre3r[ws][0][lane];
                p0[0] = aa0.x; p0[32] = aa0.y; p0[64] = ab0.x; p0[96] = ab0.y;
                float* p1 = &pre3r[ws][1][lane];
                p1[0] = aa1.x; p1[32] = aa1.y; p1[64] = ab1.x; p1[96] = ab1.y;
            }
            CTA_BAR();
        }
    } else {
        float2 wif[32];
#pragma unroll
        for (int k = 0; k < 32; k++)
            wif[k] = make_float2(Whh3[(size_t)lane * 32 + k], Whh3[(size_t)(32 + lane) * 32 + k]);
        const float2* swgo = &sw3go[0][lane];
        float cst = 0.f, h3loc = 0.f;
        for (int m = 0; m < NWALL; m++) {
            if (m >= 3) {
                const int rs = (m - 1) & 1, ws = m & 1;
                const float* prA = &pre3r[rs][0][lane];
                float2 aif = make_float2(prA[0],  prA[32]);
                float2 ago = make_float2(prA[64], prA[96]);
                float h = lstm32_step_sm(h3r[rs][1], wif, swgo, aif, ago, cst);
                h3r[ws][0][lane] = make_float2(h, h);
                __syncwarp();
                const float* prB = &pre3r[rs][1][lane];
                aif = make_float2(prB[0],  prB[32]);
                ago = make_float2(prB[64], prB[96]);
                h3loc = lstm32_step_sm(h3r[ws][0], wif, swgo, aif, ago, cst);
                h3r[ws][1][lane] = make_float2(h3loc, h3loc);
            }
            CTA_BAR();
        }
        out[(size_t)b * 32 + lane] = h3loc;
    }
}

// ---------------- launch ----------------
extern "C" void kernel_launch(void* const* d_in, const int* in_sizes, int n_in,
                              void* d_out, int out_size)
{
    const float* x      = (const float*)d_in[0];
    const float* conv_w = (const float*)d_in[1];
    const float* conv_b = (const float*)d_in[2];
    const float* Wih1   = (const float*)d_in[3];
    const float* Whh1   = (const float*)d_in[4];
    const float* bih1   = (const float*)d_in[5];
    const float* bhh1   = (const float*)d_in[6];
    const float* Wih2   = (const float*)d_in[7];
    const float* Whh2   = (const float*)d_in[8];
    const float* bih2   = (const float*)d_in[9];
    const float* bhh2   = (const float*)d_in[10];
    const float* Wih3   = (const float*)d_in[11];
    const float* Whh3   = (const float*)d_in[12];
    const float* bih3   = (const float*)d_in[13];
    const float* bhh3   = (const float*)d_in[14];
    float* out = (float*)d_out;

    float *conv_p, *xg1_p;
    cudaGetSymbolAddress((void**)&conv_p, g_conv);
    cudaGetSymbolAddress((void**)&xg1_p,  g_xg1);

    cudaFuncSetAttribute(conv3_kernel,  cudaFuncAttributeMaxDynamicSharedMemorySize, CV3_SMEM_BYTES);
    cudaFuncSetAttribute(xg1b_kernel,   cudaFuncAttributeMaxDynamicSharedMemorySize, XGB_SMEM_BYTES);

    // 0) prepack conv weights
    prep_w_kernel<<<320, 256>>>(conv_w);

    // 1) conv (tf32 mma, 2 CTAs/SM)
    conv3_kernel<<<dim3(4, BATCH, 2), 256, CV3_SMEM_BYTES>>>(x, conv_b);

    // 2) xg1 = seq @ Wih1^T + biases (64-row tiles, 2 CTAs/SM)
    xg1b_kernel<<<MROWS / 64, 256, XGB_SMEM_BYTES>>>(conv_p, Wih1, bih1, bhh1, xg1_p);

    // 3) fused LSTM1+2+3 -> d_out
    fused_lstm_kernel<<<BATCH, 128>>>(xg1_p, Whh1, Wih2, Whh2, bih2, bhh2,
                                      Wih3, Whh3, bih3, bhh3, out);

    (void)in_sizes; (void)n_in; (void)out_size;
}

// round 10
// speedup vs baseline: 1.6453x; 1.2055x over previous
#include <cuda_runtime.h>
#include <cuda_bf16.h>
#include <cstdint>

// Problem constants
#define BATCH   512
#define CIN     128
#define LIN     1024
#define KW      5
#define LOUT    1020
#define TSEQ    1020
#define H1      32
#define H2      16
#define H3      32
#define MROWS   (BATCH * TSEQ)   // 522240
#define NWALL   (TSEQ / 2 + 3)   // 513

// ---------------- scratch ----------------
__device__ float    g_conv[(size_t)BATCH * CIN * LOUT];
__device__ float    g_xg1 [(size_t)MROWS * 4 * H1];
__device__ uint32_t g_wtb [5 * 128 * 64];                  // bf16-pair W: [tap][co][ci/2]
__device__ uint32_t g_xp  [(size_t)BATCH * 64 * LIN];      // bf16-pair X: [b][ci/2][l]

// ---------------- helpers ----------------
__device__ __forceinline__ float sigmoid_fast(float x) {
    float e = __expf(-x);
    float r; asm("rcp.approx.f32 %0, %1;" : "=f"(r) : "f"(1.f + e));
    return r;
}
__device__ __forceinline__ float tanh_fast(float x) {
    float e = __expf(2.f * x);
    float r; asm("rcp.approx.f32 %0, %1;" : "=f"(r) : "f"(1.f + e));
    return fmaf(-2.f, r, 1.f);
}
__device__ __forceinline__ uint32_t pack_bf16(float lo, float hi) {
    uint32_t r;
    asm("cvt.rn.bf16x2.f32 %0, %1, %2;" : "=r"(r) : "f"(hi), "f"(lo));
    return r;
}
__device__ __forceinline__ void mma_bf16(float c[4], const uint32_t a[4], uint32_t b0, uint32_t b1) {
    asm volatile(
        "mma.sync.aligned.m16n8k16.row.col.f32.bf16.bf16.f32 "
        "{%0,%1,%2,%3}, {%4,%5,%6,%7}, {%8,%9}, {%0,%1,%2,%3};"
        : "+f"(c[0]), "+f"(c[1]), "+f"(c[2]), "+f"(c[3])
        : "r"(a[0]), "r"(a[1]), "r"(a[2]), "r"(a[3]), "r"(b0), "r"(b1));
}
__device__ __forceinline__ float2 ffma2(float2 a, float2 b, float2 c) {
    unsigned long long ua, ub, uc, ur;
    ua = *reinterpret_cast<unsigned long long*>(&a);
    ub = *reinterpret_cast<unsigned long long*>(&b);
    uc = *reinterpret_cast<unsigned long long*>(&c);
    asm("fma.rn.f32x2 %0, %1, %2, %3;" : "=l"(ur) : "l"(ua), "l"(ub), "l"(uc));
    return *reinterpret_cast<float2*>(&ur);
}
__device__ __forceinline__ uint32_t smem_u32(const void* p) {
    uint32_t a;
    asm("{ .reg .u64 t; cvta.to.shared.u64 t, %1; cvt.u32.u64 %0, t; }" : "=r"(a) : "l"(p));
    return a;
}
__device__ __forceinline__ void cp16(uint32_t dst, const void* src) {
    asm volatile("cp.async.ca.shared.global [%0], [%1], 16;" :: "r"(dst), "l"(src));
}
__device__ __forceinline__ void cp16n(uint32_t dst, const void* src, int nbytes) {
    asm volatile("cp.async.ca.shared.global [%0], [%1], 16, %2;" :: "r"(dst), "l"(src), "r"(nbytes));
}
#define CTA_BAR() asm volatile("bar.sync 0;" ::: "memory")

// H=32 LSTM cell step (fused kernel; unchanged)
__device__ __forceinline__ float lstm32_step_sm(
    const float2* __restrict__ hp,
    const float2* __restrict__ wif,
    const float2* __restrict__ swgo,
    float2 aif, float2 ago, float& cst)
{
    float2 aifB = make_float2(0.f, 0.f), agoB = make_float2(0.f, 0.f);
#pragma unroll
    for (int k = 0; k < 16; k++) {
        float2 hv = hp[k];
        aif = ffma2(hv, wif[k], aif);
        ago = ffma2(hv, swgo[k * 32], ago);
    }
#pragma unroll
    for (int k = 16; k < 32; k++) {
        float2 hv = hp[k];
        aifB = ffma2(hv, wif[k], aifB);
        agoB = ffma2(hv, swgo[k * 32], agoB);
    }
    float ig = sigmoid_fast(aif.x + aifB.x);
    float fg = sigmoid_fast(aif.y + aifB.y);
    float gg = tanh_fast(ago.x + agoB.x);
    float og = sigmoid_fast(ago.y + agoB.y);
    cst = fg * cst + ig * gg;
    return og * tanh_fast(cst);
}

// =====================================================================
// Prepack kernels (bf16 pairs)
// =====================================================================
__global__ void prep_wb_kernel(const float* __restrict__ w) {
    int i = blockIdx.x * 256 + threadIdx.x;
    if (i < 5 * 128 * 64) {
        int kp = i & 63;
        int r  = i >> 6;
        int co  = r & 127;
        int tap = r >> 7;
        float lo = w[((size_t)co * 128 + 2 * kp)     * 5 + tap];
        float hi = w[((size_t)co * 128 + 2 * kp + 1) * 5 + tap];
        g_wtb[i] = pack_bf16(lo, hi);
    }
}
__global__ __launch_bounds__(256) void prep_xp_kernel(const float* __restrict__ x) {
    size_t idx = (size_t)blockIdx.x * 256 + threadIdx.x;
    if (idx < (size_t)BATCH * 64 * LIN) {
        int l  = (int)(idx & 1023);
        size_t r = idx >> 10;
        int cp = (int)(r & 63);
        size_t b = r >> 6;
        float lo = x[(b * 128 + 2 * cp)     * LIN + l];
        float hi = x[(b * 128 + 2 * cp + 1) * LIN + l];
        g_xp[idx] = pack_bf16(lo, hi);
    }
}

// =====================================================================
// conv1d via bf16 m16n8k16 MMA, 64co x 256l tile, 2 CTAs/SM,
// cp.async double-buffered. grid (4, 512, 2), block 256.
// smem/stage: Ws 320rows x 12 u32 + Xs 8rows x 264 u32
// =====================================================================
#define CV4_WS_ST   (320 * 12)       // 3840 u32
#define CV4_XS_ST   (8 * 264)        // 2112 u32
#define CV4_XS_BASE (2 * CV4_WS_ST)
#define CV4_SMEM_BYTES ((2 * CV4_WS_ST + 2 * CV4_XS_ST) * 4)   // 47616

__global__ __launch_bounds__(256, 2) void conv4_kernel(
    const float* __restrict__ bias)
{
    extern __shared__ uint32_t smu[];
    const uint32_t sbase = smem_u32(smu);
    const uint32_t* Su = smu;

    const int b   = blockIdx.y;
    const int lb  = blockIdx.x * 256;
    const int co0 = blockIdx.z * 64;
    const int tid = threadIdx.x;
    const int warp = tid >> 5;
    const int lane = tid & 31;
    const int g   = lane >> 2;
    const int t4  = lane & 3;
    const int warp_m = warp >> 2;   // 0..1 : 32 co
    const int warp_n = warp & 3;    // 0..3 : 64 l

    float acc[2][8][4];
#pragma unroll
    for (int mi = 0; mi < 2; mi++)
#pragma unroll
        for (int ni = 0; ni < 8; ni++)
#pragma unroll
            for (int e = 0; e < 4; e++) acc[mi][ni][e] = 0.f;

    const uint32_t* xpb = g_xp + (size_t)b * 64 * LIN;

    auto issue_chunk = [&](int c, int s) {
        // W: 320 rows x 8 u32 (32B = 2 cp16) -> stride-12 smem rows
#pragma unroll
        for (int i = 0; i < 3; i++) {
            int v = tid + i * 256;           // 0..639
            if (v < 640) {
                int row = v >> 1, half = v & 1;
                int tap = row >> 6, col = row & 63;
                uint32_t d = sbase + (uint32_t)(s * CV4_WS_ST + row * 12 + half * 4) * 4;
                cp16(d, g_wtb + (size_t)(tap * 128 + co0 + col) * 64 + c * 8 + half * 4);
            }
        }
        // X: 8 pair-rows x 260 u32 (65 cp16 each)
#pragma unroll
        for (int i = 0; i < 3; i++) {
            int v = tid + i * 256;
            if (v < 520) {
                int row = v / 65, q = v - row * 65;
                int gl = lb + q * 4;
                int nb = (LIN - gl) * 4;
                nb = nb < 0 ? 0 : (nb > 16 ? 16 : nb);
                const uint32_t* sp = (nb > 0) ? (xpb + (size_t)(c * 8 + row) * LIN + gl) : xpb;
                uint32_t d = sbase + (uint32_t)(CV4_XS_BASE + s * CV4_XS_ST + row * 264 + q * 4) * 4;
                cp16n(d, sp, nb);
            }
        }
    };

    for (int c = 0; c < 8; c++) {
        const int s = c & 1;
        if (c == 0) {
            issue_chunk(0, 0);
            asm volatile("cp.async.commit_group;");
        }
        if (c + 1 < 8) {
            issue_chunk(c + 1, s ^ 1);
            asm volatile("cp.async.commit_group;");
            asm volatile("cp.async.wait_group 1;");
        } else {
            asm volatile("cp.async.wait_group 0;");
        }
        __syncthreads();

        const uint32_t* Wst = Su + s * CV4_WS_ST;
        const uint32_t* Xst = Su + CV4_XS_BASE + s * CV4_XS_ST;
#pragma unroll
        for (int tap = 0; tap < 5; tap++) {
            uint32_t a[2][4];
#pragma unroll
            for (int mi = 0; mi < 2; mi++) {
                int row = tap * 64 + warp_m * 32 + mi * 16;
                a[mi][0] = Wst[(row + g)     * 12 + t4];
                a[mi][1] = Wst[(row + 8 + g) * 12 + t4];
                a[mi][2] = Wst[(row + g)     * 12 + t4 + 4];
                a[mi][3] = Wst[(row + 8 + g) * 12 + t4 + 4];
            }
#pragma unroll
            for (int ni = 0; ni < 8; ni++) {
                int col = warp_n * 64 + ni * 8 + g + tap;
                uint32_t b0 = Xst[t4 * 264 + col];
                uint32_t b1 = Xst[(t4 + 4) * 264 + col];
                mma_bf16(acc[0][ni], a[0], b0, b1);
                mma_bf16(acc[1][ni], a[1], b0, b1);
            }
        }
        __syncthreads();
    }

    float* ob = g_conv + (size_t)b * (CIN * LOUT);
#pragma unroll
    for (int mi = 0; mi < 2; mi++) {
        int row0 = co0 + warp_m * 32 + mi * 16 + g;
        float bv0 = bias[row0];
        float bv1 = bias[row0 + 8];
#pragma unroll
        for (int ni = 0; ni < 8; ni++) {
            int l = lb + warp_n * 64 + ni * 8 + 2 * t4;
            if (l + 1 < LOUT) {
                *reinterpret_cast<float2*>(ob + (size_t)row0 * LOUT + l) =
                    make_float2(acc[mi][ni][0] + bv0, acc[mi][ni][1] + bv0);
                *reinterpret_cast<float2*>(ob + (size_t)(row0 + 8) * LOUT + l) =
                    make_float2(acc[mi][ni][2] + bv1, acc[mi][ni][3] + bv1);
            } else if (l < LOUT) {
                ob[(size_t)row0 * LOUT + l]       = acc[mi][ni][0] + bv0;
                ob[(size_t)(row0 + 8) * LOUT + l] = acc[mi][ni][2] + bv1;
            }
        }
    }
}

// =====================================================================
// xg1 via bf16 m16n8k16 MMA, 128-row tile, 2 CTAs/SM. grid 4080.
// smem: Aspair[128][68] + Bspair[128][68] u32 = 69632 B
// =====================================================================
#define XGC_STRIDE 68
#define XGC_SMEM_BYTES (2 * 128 * XGC_STRIDE * 4)   // 69632

__global__ __launch_bounds__(256, 2) void xg1c_kernel(
    const float* __restrict__ A, const float* __restrict__ W,
    const float* __restrict__ b1, const float* __restrict__ b2,
    float* __restrict__ C)
{
    extern __shared__ uint32_t smu[];
    uint32_t* As = smu;                        // [128][68]
    uint32_t* Bs = smu + 128 * XGC_STRIDE;     // [128][68]

    const int row0 = blockIdx.x * 128;
    const int tid  = threadIdx.x;
    const int warp = tid >> 5;
    const int lane = tid & 31;
    const int g    = lane >> 2;
    const int t4   = lane & 3;
    const int warp_m = warp >> 1;   // 0..3 : 32 rows
    const int warp_n = warp & 1;    // 0..1 : 64 cols

    for (int v = tid; v < 128 * 64; v += 256) {
        int r  = v >> 6;
        int kp = v & 63;
        float2 av = *reinterpret_cast<const float2*>(A + (size_t)(row0 + r) * 128 + 2 * kp);
        As[r * XGC_STRIDE + kp] = pack_bf16(av.x, av.y);
        float2 wv = *reinterpret_cast<const float2*>(W + (size_t)r * 128 + 2 * kp);
        Bs[r * XGC_STRIDE + kp] = pack_bf16(wv.x, wv.y);
    }
    __syncthreads();

    float acc[2][8][4];
#pragma unroll
    for (int mi = 0; mi < 2; mi++)
#pragma unroll
        for (int ni = 0; ni < 8; ni++)
#pragma unroll
            for (int e = 0; e < 4; e++) acc[mi][ni][e] = 0.f;

#pragma unroll
    for (int k0 = 0; k0 < 64; k0 += 8) {
        uint32_t a[2][4];
#pragma unroll
        for (int mi = 0; mi < 2; mi++) {
            int row = warp_m * 32 + mi * 16;
            a[mi][0] = As[(row + g)     * XGC_STRIDE + k0 + t4];
            a[mi][1] = As[(row + 8 + g) * XGC_STRIDE + k0 + t4];
            a[mi][2] = As[(row + g)     * XGC_STRIDE + k0 + t4 + 4];
            a[mi][3] = As[(row + 8 + g) * XGC_STRIDE + k0 + t4 + 4];
        }
#pragma unroll
        for (int ni = 0; ni < 8; ni++) {
            int n = warp_n * 64 + ni * 8 + g;
            uint32_t b0 = Bs[n * XGC_STRIDE + k0 + t4];
            uint32_t b1 = Bs[n * XGC_STRIDE + k0 + t4 + 4];
            mma_bf16(acc[0][ni], a[0], b0, b1);
            mma_bf16(acc[1][ni], a[1], b0, b1);
        }
    }

#pragma unroll
    for (int mi = 0; mi < 2; mi++) {
        int r0 = row0 + warp_m * 32 + mi * 16 + g;
#pragma unroll
        for (int ni = 0; ni < 8; ni++) {
            int n = warp_n * 64 + ni * 8 + 2 * t4;
            float bb0 = b1[n] + b2[n];
            float bb1 = b1[n + 1] + b2[n + 1];
            *reinterpret_cast<float2*>(C + (size_t)r0 * 128 + n) =
                make_float2(acc[mi][ni][0] + bb0, acc[mi][ni][1] + bb1);
            *reinterpret_cast<float2*>(C + (size_t)(r0 + 8) * 128 + n) =
                make_float2(acc[mi][ni][2] + bb0, acc[mi][ni][3] + bb1);
        }
    }
}

// =====================================================================
// Fused LSTM1+2+3 (unchanged from R8/R9)
// =====================================================================
__global__ __launch_bounds__(128, 4) void fused_lstm_kernel(
    const float* __restrict__ xg1,
    const float* __restrict__ Whh1,
    const float* __restrict__ Wih2, const float* __restrict__ Whh2,
    const float* __restrict__ bih2, const float* __restrict__ bhh2,
    const float* __restrict__ Wih3, const float* __restrict__ Whh3,
    const float* __restrict__ bih3, const float* __restrict__ bhh3,
    float* __restrict__ out)
{
    __shared__ __align__(16) float2 sw1go[32][32];
    __shared__ __align__(16) float2 sw3go[32][32];
    __shared__ __align__(16) float2 sw2h [16][32];
    __shared__ __align__(16) float2 h1r[2][2][32];
    __shared__ __align__(16) float2 h2r[2][2][16];
    __shared__ __align__(16) float2 h3r[2][2][32];
    __shared__ __align__(16) float  pre3r[2][2][128];

    const int tid  = threadIdx.x;
    const int wid  = tid >> 5;
    const int lane = tid & 31;
    const int b    = blockIdx.x;
    const int role = (wid + b) & 3;

    for (int v = tid; v < 1024; v += 128) {
        int k = v >> 5, j = v & 31;
        sw1go[k][j] = make_float2(Whh1[(size_t)(64 + j) * 32 + k], Whh1[(size_t)(96 + j) * 32 + k]);
        sw3go[k][j] = make_float2(Whh3[(size_t)(64 + j) * 32 + k], Whh3[(size_t)(96 + j) * 32 + k]);
    }
    for (int v = tid; v < 512; v += 128) {
        int k = v >> 5, j = v & 31;
        sw2h[k][j] = make_float2(Whh2[(size_t)j * 16 + k], Whh2[(size_t)(32 + j) * 16 + k]);
    }
    for (int v = tid; v < 128; v += 128) h1r[(v >> 6) & 1][(v >> 5) & 1][v & 31] = make_float2(0.f, 0.f);
    if (tid < 64)  h2r[(tid >> 5) & 1][(tid >> 4) & 1][tid & 15] = make_float2(0.f, 0.f);
    for (int v = tid; v < 128; v += 128) h3r[(v >> 6) & 1][(v >> 5) & 1][v & 31] = make_float2(0.f, 0.f);
    for (int v = tid; v < 512; v += 128) pre3r[(v >> 8) & 1][(v >> 7) & 1][v & 127] = 0.f;
    __syncthreads();

    if (role == 0) {
        float2 wif[32];
#pragma unroll
        for (int k = 0; k < 32; k++)
            wif[k] = make_float2(Whh1[(size_t)lane * 32 + k], Whh1[(size_t)(32 + lane) * 32 + k]);
        const float2* swgo = &sw1go[0][lane];
        const float* xb = xg1 + (size_t)b * TSEQ * 128 + lane;
        float pA0 = xb[0],   pA1 = xb[32],  pA2 = xb[64],  pA3 = xb[96];
        float pB0 = xb[128], pB1 = xb[160], pB2 = xb[192], pB3 = xb[224];
        float cst = 0.f;
        for (int m = 0; m < NWALL; m++) {
            if (m <= 509) {
                const int rs = (m - 1) & 1, ws = m & 1;
                float2 aifA = make_float2(pA0, pA1), agoA = make_float2(pA2, pA3);
                float2 aifB = make_float2(pB0, pB1), agoB = make_float2(pB2, pB3);
                if (m < 509) {
                    const float* xn = xb + (size_t)(2 * m + 2) * 128;
                    pA0 = __ldg(xn);       pA1 = __ldg(xn + 32);
                    pA2 = __ldg(xn + 64);  pA3 = __ldg(xn + 96);
                    pB0 = __ldg(xn + 128); pB1 = __ldg(xn + 160);
                    pB2 = __ldg(xn + 192); pB3 = __ldg(xn + 224);
                }
                float h = lstm32_step_sm(h1r[rs][1], wif, swgo, aifA, agoA, cst);
                h1r[ws][0][lane] = make_float2(h, h);
                __syncwarp();
                h = lstm32_step_sm(h1r[ws][0], wif, swgo, aifB, agoB, cst);
                h1r[ws][1][lane] = make_float2(h, h);
            }
            CTA_BAR();
        }
    } else if (role == 1) {
        const int pa = lane;
        const int pb = 32 + lane;
        float2 wi[32];
#pragma unroll
        for (int k = 0; k < 32; k++)
            wi[k] = make_float2(Wih2[(size_t)pa * 32 + k], Wih2[(size_t)pb * 32 + k]);
        const float2* swh = &sw2h[0][lane];
        const float2 bias2 = make_float2(bih2[pa] + bhh2[pa], bih2[pb] + bhh2[pb]);
        float cst = 0.f;
        for (int m = 0; m < NWALL; m++) {
            if (m >= 1 && m <= 510) {
                const int rs = (m - 1) & 1, ws = m & 1;
#pragma unroll
                for (int st = 0; st < 2; st++) {
                    float2 acc = bias2, accB = make_float2(0.f, 0.f);
                    const float2* h1p = h1r[rs][st];
#pragma unroll
                    for (int k = 0; k < 16; k++)
                        acc = ffma2(h1p[k], wi[k], acc);
#pragma unroll
                    for (int k = 16; k < 32; k++)
                        accB = ffma2(h1p[k], wi[k], accB);
                    const float2* h2p = (st == 0) ? h2r[rs][1] : h2r[ws][0];
#pragma unroll
                    for (int k = 0; k < 16; k++)
                        accB = ffma2(h2p[k], swh[k * 32], accB);
                    float va = acc.x + accB.x;
                    float vb = acc.y + accB.y;
                    float fpre = __shfl_sync(0xffffffffu, va, (lane & 15) + 16);
                    float opre = __shfl_sync(0xffffffffu, vb, (lane & 15) + 16);
                    if (lane < 16) {
                        float ig = sigmoid_fast(va);
                        float gg = tanh_fast(vb);
                        float fg = sigmoid_fast(fpre);
                        float og = sigmoid_fast(opre);
                        cst = fg * cst + ig * gg;
                        float h = og * tanh_fast(cst);
                        h2r[ws][st][lane] = make_float2(h, h);
                    }
                    __syncwarp();
                }
            }
            CTA_BAR();
        }
    } else if (role == 2) {
        float2 wa[16], wb[16];
#pragma unroll
        for (int k = 0; k < 16; k++) {
            wa[k] = make_float2(Wih3[(size_t)lane * 16 + k],        Wih3[(size_t)(32 + lane) * 16 + k]);
            wb[k] = make_float2(Wih3[(size_t)(64 + lane) * 16 + k], Wih3[(size_t)(96 + lane) * 16 + k]);
        }
        const float2 b3a = make_float2(bih3[lane] + bhh3[lane],           bih3[32 + lane] + bhh3[32 + lane]);
        const float2 b3b = make_float2(bih3[64 + lane] + bhh3[64 + lane], bih3[96 + lane] + bhh3[96 + lane]);
        for (int m = 0; m < NWALL; m++) {
            if (m >= 2 && m <= 511) {
                const int rs = (m - 1) & 1, ws = m & 1;
                float2 aa0 = b3a, ab0 = b3b, aa1 = b3a, ab1 = b3b;
                const float2* h2p0 = h2r[rs][0];
                const float2* h2p1 = h2r[rs][1];
#pragma unroll
                for (int k = 0; k < 16; k++) {
                    float2 hv0 = h2p0[k], hv1 = h2p1[k];
                    aa0 = ffma2(hv0, wa[k], aa0);
                    ab0 = ffma2(hv0, wb[k], ab0);
                    aa1 = ffma2(hv1, wa[k], aa1);
                    ab1 = ffma2(hv1, wb[k], ab1);
                }
                float* p0 = &pre3r[ws][0][lane];
                p0[0] = aa0.x; p0[32] = aa0.y; p0[64] = ab0.x; p0[96] = ab0.y;
                float* p1 = &pre3r[ws][1][lane];
                p1[0] = aa1.x; p1[32] = aa1.y; p1[64] = ab1.x; p1[96] = ab1.y;
            }
            CTA_BAR();
        }
    } else {
        float2 wif[32];
#pragma unroll
        for (int k = 0; k < 32; k++)
            wif[k] = make_float2(Whh3[(size_t)lane * 32 + k], Whh3[(size_t)(32 + lane) * 32 + k]);
        const float2* swgo = &sw3go[0][lane];
        float cst = 0.f, h3loc = 0.f;
        for (int m = 0; m < NWALL; m++) {
            if (m >= 3) {
                const int rs = (m - 1) & 1, ws = m & 1;
                const float* prA = &pre3r[rs][0][lane];
                float2 aif = make_float2(prA[0],  prA[32]);
                float2 ago = make_float2(prA[64], prA[96]);
                float h = lstm32_step_sm(h3r[rs][1], wif, swgo, aif, ago, cst);
                h3r[ws][0][lane] = make_float2(h, h);
                __syncwarp();
                const float* prB = &pre3r[rs][1][lane];
                aif = make_float2(prB[0],  prB[32]);
                ago = make_float2(prB[64], prB[96]);
                h3loc = lstm32_step_sm(h3r[ws][0], wif, swgo, aif, ago, cst);
                h3r[ws][1][lane] = make_float2(h3loc, h3loc);
            }
            CTA_BAR();
        }
        out[(size_t)b * 32 + lane] = h3loc;
    }
}

// ---------------- launch ----------------
extern "C" void kernel_launch(void* const* d_in, const int* in_sizes, int n_in,
                              void* d_out, int out_size)
{
    const float* x      = (const float*)d_in[0];
    const float* conv_w = (const float*)d_in[1];
    const float* conv_b = (const float*)d_in[2];
    const float* Wih1   = (const float*)d_in[3];
    const float* Whh1   = (const float*)d_in[4];
    const float* bih1   = (const float*)d_in[5];
    const float* bhh1   = (const float*)d_in[6];
    const float* Wih2   = (const float*)d_in[7];
    const float* Whh2   = (const float*)d_in[8];
    const float* bih2   = (const float*)d_in[9];
    const float* bhh2   = (const float*)d_in[10];
    const float* Wih3   = (const float*)d_in[11];
    const float* Whh3   = (const float*)d_in[12];
    const float* bih3   = (const float*)d_in[13];
    const float* bhh3   = (const float*)d_in[14];
    float* out = (float*)d_out;

    float *conv_p, *xg1_p;
    cudaGetSymbolAddress((void**)&conv_p, g_conv);
    cudaGetSymbolAddress((void**)&xg1_p,  g_xg1);

    cudaFuncSetAttribute(conv4_kernel, cudaFuncAttributeMaxDynamicSharedMemorySize, CV4_SMEM_BYTES);
    cudaFuncSetAttribute(xg1c_kernel,  cudaFuncAttributeMaxDynamicSharedMemorySize, XGC_SMEM_BYTES);

    // 0) prepack: W (bf16 pairs) + X (bf16 pairs across ci)
    prep_wb_kernel<<<160, 256>>>(conv_w);
    prep_xp_kernel<<<(int)(((size_t)BATCH * 64 * LIN + 255) / 256), 256>>>(x);

    // 1) conv (bf16 m16n8k16, 2 CTAs/SM)
    conv4_kernel<<<dim3(4, BATCH, 2), 256, CV4_SMEM_BYTES>>>(conv_b);

    // 2) xg1 = seq @ Wih1^T + biases (bf16, 2 CTAs/SM)
    xg1c_kernel<<<MROWS / 128, 256, XGC_SMEM_BYTES>>>(conv_p, Wih1, bih1, bhh1, xg1_p);

    // 3) fused LSTM1+2+3 -> d_out
    fused_lstm_kernel<<<BATCH, 128>>>(xg1_p, Whh1, Wih2, Whh2, bih2, bhh2,
                                      Wih3, Whh3, bih3, bhh3, out);

    (void)in_sizes; (void)n_in; (void)out_size;
}

// round 11
// speedup vs baseline: 1.6667x; 1.0130x over previous
#include <cuda_runtime.h>
#include <cuda_bf16.h>
#include <cstdint>

// Problem constants
#define BATCH   512
#define CIN     128
#define LIN     1024
#define KW      5
#define LOUT    1020
#define TSEQ    1020
#define H1      32
#define H2      16
#define H3      32
#define MROWS   (BATCH * TSEQ)   // 522240
#define NWALL   (TSEQ / 2 + 3)   // 513

// ---------------- scratch ----------------
__device__ uint32_t g_convb[(size_t)BATCH * 64 * LOUT];    // bf16-pair conv out: pair idx = (co*1020+l)/2
__device__ float    g_xg1 [(size_t)MROWS * 4 * H1];
__device__ uint32_t g_wtb [5 * 128 * 64];                  // bf16-pair W: [tap][co][ci/2]
__device__ uint32_t g_xp  [(size_t)BATCH * 64 * LIN];      // bf16-pair X: [b][ci/2][l]

// ---------------- helpers ----------------
__device__ __forceinline__ float sigmoid_fast(float x) {
    float e = __expf(-x);
    float r; asm("rcp.approx.f32 %0, %1;" : "=f"(r) : "f"(1.f + e));
    return r;
}
__device__ __forceinline__ float tanh_fast(float x) {
    float e = __expf(2.f * x);
    float r; asm("rcp.approx.f32 %0, %1;" : "=f"(r) : "f"(1.f + e));
    return fmaf(-2.f, r, 1.f);
}
__device__ __forceinline__ uint32_t pack_bf16(float lo, float hi) {
    uint32_t r;
    asm("cvt.rn.bf16x2.f32 %0, %1, %2;" : "=r"(r) : "f"(hi), "f"(lo));
    return r;
}
__device__ __forceinline__ void mma_bf16(float c[4], const uint32_t a[4], uint32_t b0, uint32_t b1) {
    asm volatile(
        "mma.sync.aligned.m16n8k16.row.col.f32.bf16.bf16.f32 "
        "{%0,%1,%2,%3}, {%4,%5,%6,%7}, {%8,%9}, {%0,%1,%2,%3};"
        : "+f"(c[0]), "+f"(c[1]), "+f"(c[2]), "+f"(c[3])
        : "r"(a[0]), "r"(a[1]), "r"(a[2]), "r"(a[3]), "r"(b0), "r"(b1));
}
__device__ __forceinline__ float2 ffma2(float2 a, float2 b, float2 c) {
    unsigned long long ua, ub, uc, ur;
    ua = *reinterpret_cast<unsigned long long*>(&a);
    ub = *reinterpret_cast<unsigned long long*>(&b);
    uc = *reinterpret_cast<unsigned long long*>(&c);
    asm("fma.rn.f32x2 %0, %1, %2, %3;" : "=l"(ur) : "l"(ua), "l"(ub), "l"(uc));
    return *reinterpret_cast<float2*>(&ur);
}
__device__ __forceinline__ uint32_t smem_u32(const void* p) {
    uint32_t a;
    asm("{ .reg .u64 t; cvta.to.shared.u64 t, %1; cvt.u32.u64 %0, t; }" : "=r"(a) : "l"(p));
    return a;
}
__device__ __forceinline__ void cp16(uint32_t dst, const void* src) {
    asm volatile("cp.async.ca.shared.global [%0], [%1], 16;" :: "r"(dst), "l"(src));
}
__device__ __forceinline__ void cp16n(uint32_t dst, const void* src, int nbytes) {
    asm volatile("cp.async.ca.shared.global [%0], [%1], 16, %2;" :: "r"(dst), "l"(src), "r"(nbytes));
}
#define CTA_BAR() asm volatile("bar.sync 0;" ::: "memory")

// H=32 LSTM cell step (fused kernel; unchanged)
__device__ __forceinline__ float lstm32_step_sm(
    const float2* __restrict__ hp,
    const float2* __restrict__ wif,
    const float2* __restrict__ swgo,
    float2 aif, float2 ago, float& cst)
{
    float2 aifB = make_float2(0.f, 0.f), agoB = make_float2(0.f, 0.f);
#pragma unroll
    for (int k = 0; k < 16; k++) {
        float2 hv = hp[k];
        aif = ffma2(hv, wif[k], aif);
        ago = ffma2(hv, swgo[k * 32], ago);
    }
#pragma unroll
    for (int k = 16; k < 32; k++) {
        float2 hv = hp[k];
        aifB = ffma2(hv, wif[k], aifB);
        agoB = ffma2(hv, swgo[k * 32], agoB);
    }
    float ig = sigmoid_fast(aif.x + aifB.x);
    float fg = sigmoid_fast(aif.y + aifB.y);
    float gg = tanh_fast(ago.x + agoB.x);
    float og = sigmoid_fast(ago.y + agoB.y);
    cst = fg * cst + ig * gg;
    return og * tanh_fast(cst);
}

// =====================================================================
// Prepack kernels (bf16 pairs)
// =====================================================================
__global__ void prep_wb_kernel(const float* __restrict__ w) {
    int i = blockIdx.x * 256 + threadIdx.x;
    if (i < 5 * 128 * 64) {
        int kp = i & 63;
        int r  = i >> 6;
        int co  = r & 127;
        int tap = r >> 7;
        float lo = w[((size_t)co * 128 + 2 * kp)     * 5 + tap];
        float hi = w[((size_t)co * 128 + 2 * kp + 1) * 5 + tap];
        g_wtb[i] = pack_bf16(lo, hi);
    }
}
__global__ __launch_bounds__(256) void prep_xp_kernel(const float* __restrict__ x) {
    size_t idx = (size_t)blockIdx.x * 256 + threadIdx.x;
    if (idx < (size_t)BATCH * 64 * LIN) {
        int l  = (int)(idx & 1023);
        size_t r = idx >> 10;
        int cp = (int)(r & 63);
        size_t b = r >> 6;
        float lo = x[(b * 128 + 2 * cp)     * LIN + l];
        float hi = x[(b * 128 + 2 * cp + 1) * LIN + l];
        g_xp[idx] = pack_bf16(lo, hi);
    }
}

// =====================================================================
// conv1d via bf16 m16n8k16 MMA, 64co x 256l tile, 2 CTAs/SM,
// cp.async double-buffered. Output: PACKED bf16 pairs (adjacent l).
// =====================================================================
#define CV4_WS_ST   (320 * 12)       // 3840 u32
#define CV4_XS_ST   (8 * 264)        // 2112 u32
#define CV4_XS_BASE (2 * CV4_WS_ST)
#define CV4_SMEM_BYTES ((2 * CV4_WS_ST + 2 * CV4_XS_ST) * 4)   // 47616

__global__ __launch_bounds__(256, 2) void conv4_kernel(
    const float* __restrict__ bias)
{
    extern __shared__ uint32_t smu[];
    const uint32_t sbase = smem_u32(smu);
    const uint32_t* Su = smu;

    const int b   = blockIdx.y;
    const int lb  = blockIdx.x * 256;
    const int co0 = blockIdx.z * 64;
    const int tid = threadIdx.x;
    const int warp = tid >> 5;
    const int lane = tid & 31;
    const int g   = lane >> 2;
    const int t4  = lane & 3;
    const int warp_m = warp >> 2;   // 0..1 : 32 co
    const int warp_n = warp & 3;    // 0..3 : 64 l

    float acc[2][8][4];
#pragma unroll
    for (int mi = 0; mi < 2; mi++)
#pragma unroll
        for (int ni = 0; ni < 8; ni++)
#pragma unroll
            for (int e = 0; e < 4; e++) acc[mi][ni][e] = 0.f;

    const uint32_t* xpb = g_xp + (size_t)b * 64 * LIN;

    auto issue_chunk = [&](int c, int s) {
#pragma unroll
        for (int i = 0; i < 3; i++) {
            int v = tid + i * 256;
            if (v < 640) {
                int row = v >> 1, half = v & 1;
                int tap = row >> 6, col = row & 63;
                uint32_t d = sbase + (uint32_t)(s * CV4_WS_ST + row * 12 + half * 4) * 4;
                cp16(d, g_wtb + (size_t)(tap * 128 + co0 + col) * 64 + c * 8 + half * 4);
            }
        }
#pragma unroll
        for (int i = 0; i < 3; i++) {
            int v = tid + i * 256;
            if (v < 520) {
                int row = v / 65, q = v - row * 65;
                int gl = lb + q * 4;
                int nb = (LIN - gl) * 4;
                nb = nb < 0 ? 0 : (nb > 16 ? 16 : nb);
                const uint32_t* sp = (nb > 0) ? (xpb + (size_t)(c * 8 + row) * LIN + gl) : xpb;
                uint32_t d = sbase + (uint32_t)(CV4_XS_BASE + s * CV4_XS_ST + row * 264 + q * 4) * 4;
                cp16n(d, sp, nb);
            }
        }
    };

    for (int c = 0; c < 8; c++) {
        const int s = c & 1;
        if (c == 0) {
            issue_chunk(0, 0);
            asm volatile("cp.async.commit_group;");
        }
        if (c + 1 < 8) {
            issue_chunk(c + 1, s ^ 1);
            asm volatile("cp.async.commit_group;");
            asm volatile("cp.async.wait_group 1;");
        } else {
            asm volatile("cp.async.wait_group 0;");
        }
        __syncthreads();

        const uint32_t* Wst = Su + s * CV4_WS_ST;
        const uint32_t* Xst = Su + CV4_XS_BASE + s * CV4_XS_ST;
#pragma unroll
        for (int tap = 0; tap < 5; tap++) {
            uint32_t a[2][4];
#pragma unroll
            for (int mi = 0; mi < 2; mi++) {
                int row = tap * 64 + warp_m * 32 + mi * 16;
                a[mi][0] = Wst[(row + g)     * 12 + t4];
                a[mi][1] = Wst[(row + 8 + g) * 12 + t4];
                a[mi][2] = Wst[(row + g)     * 12 + t4 + 4];
                a[mi][3] = Wst[(row + 8 + g) * 12 + t4 + 4];
            }
#pragma unroll
            for (int ni = 0; ni < 8; ni++) {
                int col = warp_n * 64 + ni * 8 + g + tap;
                uint32_t b0 = Xst[t4 * 264 + col];
                uint32_t b1 = Xst[(t4 + 4) * 264 + col];
                mma_bf16(acc[0][ni], a[0], b0, b1);
                mma_bf16(acc[1][ni], a[1], b0, b1);
            }
        }
        __syncthreads();
    }

    // ---- epilogue: +bias, pack (l, l+1) pairs to bf16x2, store u32.
    // flat pair index = co*510 + l/2 (LOUT even => pairs never straddle co rows)
    uint32_t* ob = g_convb + (size_t)b * (64 * LOUT);
#pragma unroll
    for (int mi = 0; mi < 2; mi++) {
        int row0 = co0 + warp_m * 32 + mi * 16 + g;
        float bv0 = bias[row0];
        float bv1 = bias[row0 + 8];
#pragma unroll
        for (int ni = 0; ni < 8; ni++) {
            int l = lb + warp_n * 64 + ni * 8 + 2 * t4;   // even
            if (l < LOUT) {
                ob[(size_t)row0 * 510 + (l >> 1)] =
                    pack_bf16(acc[mi][ni][0] + bv0, acc[mi][ni][1] + bv0);
                ob[(size_t)(row0 + 8) * 510 + (l >> 1)] =
                    pack_bf16(acc[mi][ni][2] + bv1, acc[mi][ni][3] + bv1);
            }
        }
    }
}

// =====================================================================
// xg1 via bf16 m16n8k16 MMA, A read directly as packed u32 pairs.
// seq row t = pairs [t*64, t*64+64) of g_convb. 128-row tile, 2 CTAs/SM.
// =====================================================================
#define XGC_STRIDE 68
#define XGC_SMEM_BYTES (2 * 128 * XGC_STRIDE * 4)   // 69632

__global__ __launch_bounds__(256, 2) void xg1d_kernel(
    const float* __restrict__ W,
    const float* __restrict__ b1, const float* __restrict__ b2,
    float* __restrict__ C)
{
    extern __shared__ uint32_t smu[];
    uint32_t* As = smu;                        // [128][68]
    uint32_t* Bs = smu + 128 * XGC_STRIDE;     // [128][68]

    const int row0 = blockIdx.x * 128;
    const int tid  = threadIdx.x;
    const int warp = tid >> 5;
    const int lane = tid & 31;
    const int g    = lane >> 2;
    const int t4   = lane & 3;
    const int warp_m = warp >> 1;
    const int warp_n = warp & 1;

    // A: direct u32 pair loads (already bf16-packed by conv)
    for (int v = tid; v < 128 * 16; v += 256) {
        int r  = v >> 4;
        int q4 = (v & 15) * 4;
        uint4 av = *reinterpret_cast<const uint4*>(g_convb + (size_t)(row0 + r) * 64 + q4);
        *reinterpret_cast<uint4*>(&As[r * XGC_STRIDE + q4]) = av;
    }
    // W: pack in-kernel (tiny, L2-resident)
    for (int v = tid; v < 128 * 64; v += 256) {
        int r  = v >> 6;
        int kp = v & 63;
        float2 wv = *reinterpret_cast<const float2*>(W + (size_t)r * 128 + 2 * kp);
        Bs[r * XGC_STRIDE + kp] = pack_bf16(wv.x, wv.y);
    }
    __syncthreads();

    float acc[2][8][4];
#pragma unroll
    for (int mi = 0; mi < 2; mi++)
#pragma unroll
        for (int ni = 0; ni < 8; ni++)
#pragma unroll
            for (int e = 0; e < 4; e++) acc[mi][ni][e] = 0.f;

#pragma unroll
    for (int k0 = 0; k0 < 64; k0 += 8) {
        uint32_t a[2][4];
#pragma unroll
        for (int mi = 0; mi < 2; mi++) {
            int row = warp_m * 32 + mi * 16;
            a[mi][0] = As[(row + g)     * XGC_STRIDE + k0 + t4];
            a[mi][1] = As[(row + 8 + g) * XGC_STRIDE + k0 + t4];
            a[mi][2] = As[(row + g)     * XGC_STRIDE + k0 + t4 + 4];
            a[mi][3] = As[(row + 8 + g) * XGC_STRIDE + k0 + t4 + 4];
        }
#pragma unroll
        for (int ni = 0; ni < 8; ni++) {
            int n = warp_n * 64 + ni * 8 + g;
            uint32_t b0 = Bs[n * XGC_STRIDE + k0 + t4];
            uint32_t b1 = Bs[n * XGC_STRIDE + k0 + t4 + 4];
            mma_bf16(acc[0][ni], a[0], b0, b1);
            mma_bf16(acc[1][ni], a[1], b0, b1);
        }
    }

#pragma unroll
    for (int mi = 0; mi < 2; mi++) {
        int r0 = row0 + warp_m * 32 + mi * 16 + g;
#pragma unroll
        for (int ni = 0; ni < 8; ni++) {
            int n = warp_n * 64 + ni * 8 + 2 * t4;
            float bb0 = b1[n] + b2[n];
            float bb1 = b1[n + 1] + b2[n + 1];
            *reinterpret_cast<float2*>(C + (size_t)r0 * 128 + n) =
                make_float2(acc[mi][ni][0] + bb0, acc[mi][ni][1] + bb1);
            *reinterpret_cast<float2*>(C + (size_t)(r0 + 8) * 128 + n) =
                make_float2(acc[mi][ni][2] + bb0, acc[mi][ni][3] + bb1);
        }
    }
}

// =====================================================================
// Fused LSTM1+2+3 (unchanged from R8-R10)
// =====================================================================
__global__ __launch_bounds__(128, 4) void fused_lstm_kernel(
    const float* __restrict__ xg1,
    const float* __restrict__ Whh1,
    const float* __restrict__ Wih2, const float* __restrict__ Whh2,
    const float* __restrict__ bih2, const float* __restrict__ bhh2,
    const float* __restrict__ Wih3, const float* __restrict__ Whh3,
    const float* __restrict__ bih3, const float* __restrict__ bhh3,
    float* __restrict__ out)
{
    __shared__ __align__(16) float2 sw1go[32][32];
    __shared__ __align__(16) float2 sw3go[32][32];
    __shared__ __align__(16) float2 sw2h [16][32];
    __shared__ __align__(16) float2 h1r[2][2][32];
    __shared__ __align__(16) float2 h2r[2][2][16];
    __shared__ __align__(16) float2 h3r[2][2][32];
    __shared__ __align__(16) float  pre3r[2][2][128];

    const int tid  = threadIdx.x;
    const int wid  = tid >> 5;
    const int lane = tid & 31;
    const int b    = blockIdx.x;
    const int role = (wid + b) & 3;

    for (int v = tid; v < 1024; v += 128) {
        int k = v >> 5, j = v & 31;
        sw1go[k][j] = make_float2(Whh1[(size_t)(64 + j) * 32 + k], Whh1[(size_t)(96 + j) * 32 + k]);
        sw3go[k][j] = make_float2(Whh3[(size_t)(64 + j) * 32 + k], Whh3[(size_t)(96 + j) * 32 + k]);
    }
    for (int v = tid; v < 512; v += 128) {
        int k = v >> 5, j = v & 31;
        sw2h[k][j] = make_float2(Whh2[(size_t)j * 16 + k], Whh2[(size_t)(32 + j) * 16 + k]);
    }
    for (int v = tid; v < 128; v += 128) h1r[(v >> 6) & 1][(v >> 5) & 1][v & 31] = make_float2(0.f, 0.f);
    if (tid < 64)  h2r[(tid >> 5) & 1][(tid >> 4) & 1][tid & 15] = make_float2(0.f, 0.f);
    for (int v = tid; v < 128; v += 128) h3r[(v >> 6) & 1][(v >> 5) & 1][v & 31] = make_float2(0.f, 0.f);
    for (int v = tid; v < 512; v += 128) pre3r[(v >> 8) & 1][(v >> 7) & 1][v & 127] = 0.f;
    __syncthreads();

    if (role == 0) {
        float2 wif[32];
#pragma unroll
        for (int k = 0; k < 32; k++)
            wif[k] = make_float2(Whh1[(size_t)lane * 32 + k], Whh1[(size_t)(32 + lane) * 32 + k]);
        const float2* swgo = &sw1go[0][lane];
        const float* xb = xg1 + (size_t)b * TSEQ * 128 + lane;
        float pA0 = xb[0],   pA1 = xb[32],  pA2 = xb[64],  pA3 = xb[96];
        float pB0 = xb[128], pB1 = xb[160], pB2 = xb[192], pB3 = xb[224];
        float cst = 0.f;
        for (int m = 0; m < NWALL; m++) {
            if (m <= 509) {
                const int rs = (m - 1) & 1, ws = m & 1;
                float2 aifA = make_float2(pA0, pA1), agoA = make_float2(pA2, pA3);
                float2 aifB = make_float2(pB0, pB1), agoB = make_float2(pB2, pB3);
                if (m < 509) {
                    const float* xn = xb + (size_t)(2 * m + 2) * 128;
                    pA0 = __ldg(xn);       pA1 = __ldg(xn + 32);
                    pA2 = __ldg(xn + 64);  pA3 = __ldg(xn + 96);
                    pB0 = __ldg(xn + 128); pB1 = __ldg(xn + 160);
                    pB2 = __ldg(xn + 192); pB3 = __ldg(xn + 224);
                }
                float h = lstm32_step_sm(h1r[rs][1], wif, swgo, aifA, agoA, cst);
                h1r[ws][0][lane] = make_float2(h, h);
                __syncwarp();
                h = lstm32_step_sm(h1r[ws][0], wif, swgo, aifB, agoB, cst);
                h1r[ws][1][lane] = make_float2(h, h);
            }
            CTA_BAR();
        }
    } else if (role == 1) {
        const int pa = lane;
        const int pb = 32 + lane;
        float2 wi[32];
#pragma unroll
        for (int k = 0; k < 32; k++)
            wi[k] = make_float2(Wih2[(size_t)pa * 32 + k], Wih2[(size_t)pb * 32 + k]);
        const float2* swh = &sw2h[0][lane];
        const float2 bias2 = make_float2(bih2[pa] + bhh2[pa], bih2[pb] + bhh2[pb]);
        float cst = 0.f;
        for (int m = 0; m < NWALL; m++) {
            if (m >= 1 && m <= 510) {
                const int rs = (m - 1) & 1, ws = m & 1;
#pragma unroll
                for (int st = 0; st < 2; st++) {
                    float2 acc = bias2, accB = make_float2(0.f, 0.f);
                    const float2* h1p = h1r[rs][st];
#pragma unroll
                    for (int k = 0; k < 16; k++)
                        acc = ffma2(h1p[k], wi[k], acc);
#pragma unroll
                    for (int k = 16; k < 32; k++)
                        accB = ffma2(h1p[k], wi[k], accB);
                    const float2* h2p = (st == 0) ? h2r[rs][1] : h2r[ws][0];
#pragma unroll
                    for (int k = 0; k < 16; k++)
                        accB = ffma2(h2p[k], swh[k * 32], accB);
                    float va = acc.x + accB.x;
                    float vb = acc.y + accB.y;
                    float fpre = __shfl_sync(0xffffffffu, va, (lane & 15) + 16);
                    float opre = __shfl_sync(0xffffffffu, vb, (lane & 15) + 16);
                    if (lane < 16) {
                        float ig = sigmoid_fast(va);
                        float gg = tanh_fast(vb);
                        float fg = sigmoid_fast(fpre);
                        float og = sigmoid_fast(opre);
                        cst = fg * cst + ig * gg;
                        float h = og * tanh_fast(cst);
                        h2r[ws][st][lane] = make_float2(h, h);
                    }
                    __syncwarp();
                }
            }
            CTA_BAR();
        }
    } else if (role == 2) {
        float2 wa[16], wb[16];
#pragma unroll
        for (int k = 0; k < 16; k++) {
            wa[k] = make_float2(Wih3[(size_t)lane * 16 + k],        Wih3[(size_t)(32 + lane) * 16 + k]);
            wb[k] = make_float2(Wih3[(size_t)(64 + lane) * 16 + k], Wih3[(size_t)(96 + lane) * 16 + k]);
        }
        const float2 b3a = make_float2(bih3[lane] + bhh3[lane],           bih3[32 + lane] + bhh3[32 + lane]);
        const float2 b3b = make_float2(bih3[64 + lane] + bhh3[64 + lane], bih3[96 + lane] + bhh3[96 + lane]);
        for (int m = 0; m < NWALL; m++) {
            if (m >= 2 && m <= 511) {
                const int rs = (m - 1) & 1, ws = m & 1;
                float2 aa0 = b3a, ab0 = b3b, aa1 = b3a, ab1 = b3b;
                const float2* h2p0 = h2r[rs][0];
                const float2* h2p1 = h2r[rs][1];
#pragma unroll
                for (int k = 0; k < 16; k++) {
                    float2 hv0 = h2p0[k], hv1 = h2p1[k];
                    aa0 = ffma2(hv0, wa[k], aa0);
                    ab0 = ffma2(hv0, wb[k], ab0);
                    aa1 = ffma2(hv1, wa[k], aa1);
                    ab1 = ffma2(hv1, wb[k], ab1);
                }
                float* p0 = &pre3r[ws][0][lane];
                p0[0] = aa0.x; p0[32] = aa0.y; p0[64] = ab0.x; p0[96] = ab0.y;
                float* p1 = &pre3r[ws][1][lane];
                p1[0] = aa1.x; p1[32] = aa1.y; p1[64] = ab1.x; p1[96] = ab1.y;
            }
            CTA_BAR();
        }
    } else {
        float2 wif[32];
#pragma unroll
        for (int k = 0; k < 32; k++)
            wif[k] = make_float2(Whh3[(size_t)lane * 32 + k], Whh3[(size_t)(32 + lane) * 32 + k]);
        const float2* swgo = &sw3go[0][lane];
        float cst = 0.f, h3loc = 0.f;
        for (int m = 0; m < NWALL; m++) {
            if (m >= 3) {
                const int rs = (m - 1) & 1, ws = m & 1;
                const float* prA = &pre3r[rs][0][lane];
                float2 aif = make_float2(prA[0],  prA[32]);
                float2 ago = make_float2(prA[64], prA[96]);
                float h = lstm32_step_sm(h3r[rs][1], wif, swgo, aif, ago, cst);
                h3r[ws][0][lane] = make_float2(h, h);
                __syncwarp();
                const float* prB = &pre3r[rs][1][lane];
                aif = make_float2(prB[0],  prB[32]);
                ago = make_float2(prB[64], prB[96]);
                h3loc = lstm32_step_sm(h3r[ws][0], wif, swgo, aif, ago, cst);
                h3r[ws][1][lane] = make_float2(h3loc, h3loc);
            }
            CTA_BAR();
        }
        out[(size_t)b * 32 + lane] = h3loc;
    }
}

// ---------------- launch ----------------
extern "C" void kernel_launch(void* const* d_in, const int* in_sizes, int n_in,
                              void* d_out, int out_size)
{
    const float* x      = (const float*)d_in[0];
    const float* conv_w = (const float*)d_in[1];
    const float* conv_b = (const float*)d_in[2];
    const float* Wih1   = (const float*)d_in[3];
    const float* Whh1   = (const float*)d_in[4];
    const float* bih1   = (const float*)d_in[5];
    const float* bhh1   = (const float*)d_in[6];
    const float* Wih2   = (const float*)d_in[7];
    const float* Whh2   = (const float*)d_in[8];
    const float* bih2   = (const float*)d_in[9];
    const float* bhh2   = (const float*)d_in[10];
    const float* Wih3   = (const float*)d_in[11];
    const float* Whh3   = (const float*)d_in[12];
    const float* bih3   = (const float*)d_in[13];
    const float* bhh3   = (const float*)d_in[14];
    float* out = (float*)d_out;

    float* xg1_p;
    cudaGetSymbolAddress((void**)&xg1_p, g_xg1);

    cudaFuncSetAttribute(conv4_kernel, cudaFuncAttributeMaxDynamicSharedMemorySize, CV4_SMEM_BYTES);
    cudaFuncSetAttribute(xg1d_kernel,  cudaFuncAttributeMaxDynamicSharedMemorySize, XGC_SMEM_BYTES);

    // 0) prepack: W (bf16 pairs) + X (bf16 pairs across ci)
    prep_wb_kernel<<<160, 256>>>(conv_w);
    prep_xp_kernel<<<(int)(((size_t)BATCH * 64 * LIN + 255) / 256), 256>>>(x);

    // 1) conv (bf16 m16n8k16, packed bf16 output)
    conv4_kernel<<<dim3(4, BATCH, 2), 256, CV4_SMEM_BYTES>>>(conv_b);

    // 2) xg1 = seq @ Wih1^T + biases (A read as packed pairs)
    xg1d_kernel<<<MROWS / 128, 256, XGC_SMEM_BYTES>>>(Wih1, bih1, bhh1, xg1_p);

    // 3) fused LSTM1+2+3 -> d_out
    fused_lstm_kernel<<<BATCH, 128>>>(xg1_p, Whh1, Wih2, Whh2, bih2, bhh2,
                                      Wih3, Whh3, bih3, bhh3, out);

    (void)in_sizes; (void)n_in; (void)out_size;
}